// round 3
// baseline (speedup 1.0000x reference)
#include <cuda_runtime.h>
#include <cstdint>

#define N_NODES 50000
#define N_EDGES 400000
#define D_IN    512
#define D_HID   512
#define D_OUT   256

// ---------------- scratch (device globals; no runtime alloc) ----------------
__device__ float g_h  [(size_t)N_NODES * D_HID];  // x@W1
__device__ float g_agg[(size_t)N_NODES * D_HID];  // layer-1 aggregate / relu output
__device__ float g_h2 [(size_t)N_NODES * D_OUT];  // agg@W2
__device__ float g_deg [N_NODES];
__device__ float g_dinv[N_NODES];

// ---------------- degree / norm ----------------
__global__ void k_deg_init() {
    int i = blockIdx.x * blockDim.x + threadIdx.x;
    if (i < N_NODES) g_deg[i] = 1.0f;  // self-loop contributes 1
}

__global__ void k_deg_edges(const int* __restrict__ ei) {
    int e = blockIdx.x * blockDim.x + threadIdx.x;
    if (e < N_EDGES) {
        int d = ei[N_EDGES + e];   // dst row of edge_index (int32!)
        atomicAdd(&g_deg[d], 1.0f);
    }
}

__global__ void k_dinv() {
    int i = blockIdx.x * blockDim.x + threadIdx.x;
    if (i < N_NODES) g_dinv[i] = rsqrtf(g_deg[i]);
}

// ---------------- SGEMM body: C[M,N] = A[M,K] @ B[K,N], row-major ----------------
// 64x64 tile, BK=16, 256 threads, 4x4 per thread.
template <int N, int K>
__device__ __forceinline__
void sgemm_body(const float* __restrict__ A, const float* __restrict__ B,
                float* __restrict__ C) {
    __shared__ float As[16][64];
    __shared__ float Bs[16][64 + 4];

    const int colBase = blockIdx.x * 64;
    const int rowBase = blockIdx.y * 64;
    const int tx = threadIdx.x & 15;       // N sub
    const int ty = threadIdx.x >> 4;       // M sub

    float acc[4][4] = {};

    for (int k0 = 0; k0 < K; k0 += 16) {
        #pragma unroll
        for (int i = threadIdx.x; i < 64 * 16; i += 256) {
            int m  = i >> 4;
            int kk = i & 15;
            int gm = rowBase + m;
            As[kk][m] = (gm < N_NODES) ? A[(size_t)gm * K + k0 + kk] : 0.0f;
        }
        #pragma unroll
        for (int i = threadIdx.x; i < 16 * 64; i += 256) {
            int kk = i >> 6;
            int n  = i & 63;
            Bs[kk][n] = B[(size_t)(k0 + kk) * N + colBase + n];
        }
        __syncthreads();

        #pragma unroll
        for (int kk = 0; kk < 16; kk++) {
            float a[4], b[4];
            #pragma unroll
            for (int i = 0; i < 4; i++) a[i] = As[kk][ty * 4 + i];
            #pragma unroll
            for (int j = 0; j < 4; j++) b[j] = Bs[kk][tx * 4 + j];
            #pragma unroll
            for (int i = 0; i < 4; i++)
                #pragma unroll
                for (int j = 0; j < 4; j++)
                    acc[i][j] = fmaf(a[i], b[j], acc[i][j]);
        }
        __syncthreads();
    }

    #pragma unroll
    for (int i = 0; i < 4; i++) {
        int gm = rowBase + ty * 4 + i;
        if (gm < N_NODES) {
            float* Crow = C + (size_t)gm * N + colBase + tx * 4;
            #pragma unroll
            for (int j = 0; j < 4; j++) Crow[j] = acc[i][j];
        }
    }
}

__global__ __launch_bounds__(256)
void k_sgemm_l1(const float* __restrict__ x, const float* __restrict__ W1) {
    sgemm_body<D_HID, D_IN>(x, W1, g_h);
}

__global__ __launch_bounds__(256)
void k_sgemm_l2(const float* __restrict__ W2) {
    sgemm_body<D_OUT, D_HID>(g_agg, W2, g_h2);
}

// ---------------- self-loop init + bias: dst[i,:] = h[i,:] * dinv[i]^2 + b ----------------
template <int D>
__device__ __forceinline__
void self_init_body(const float* __restrict__ h, const float* __restrict__ b,
                    float* __restrict__ dst) {
    size_t idx = (size_t)blockIdx.x * blockDim.x + threadIdx.x;
    if (idx < (size_t)N_NODES * D) {
        int i = (int)(idx / D);
        int c = (int)(idx % D);
        float s = g_dinv[i];
        dst[idx] = fmaf(h[idx], s * s, b[c]);
    }
}

__global__ void k_self_init_l1(const float* __restrict__ b1) {
    self_init_body<D_HID>(g_h, b1, g_agg);
}
__global__ void k_self_init_l2(const float* __restrict__ b2, float* __restrict__ out) {
    self_init_body<D_OUT>(g_h2, b2, out);
}

// ---------------- edge scatter: dst[d,:] += h[s,:] * dinv[s]*dinv[d] ----------------
template <int D>
__device__ __forceinline__
void scatter_body(const int* __restrict__ ei, const float* __restrict__ h,
                  float* __restrict__ dst) {
    int warp = blockIdx.x * (blockDim.x >> 5) + (threadIdx.x >> 5);
    int lane = threadIdx.x & 31;
    if (warp >= N_EDGES) return;
    int s = ei[warp];               // src (int32)
    int d = ei[N_EDGES + warp];     // dst (int32)
    float w = g_dinv[s] * g_dinv[d];
    const float* __restrict__ hs = h + (size_t)s * D;
    float* ad = dst + (size_t)d * D;
    #pragma unroll
    for (int c = lane; c < D; c += 32)
        atomicAdd(&ad[c], hs[c] * w);
}

__global__ __launch_bounds__(256)
void k_scatter_l1(const int* __restrict__ ei) {
    scatter_body<D_HID>(ei, g_h, g_agg);
}
__global__ __launch_bounds__(256)
void k_scatter_l2(const int* __restrict__ ei, float* __restrict__ out) {
    scatter_body<D_OUT>(ei, g_h2, out);
}

// ---------------- in-place relu on g_agg ----------------
__global__ void k_relu() {
    size_t idx = (size_t)blockIdx.x * blockDim.x + threadIdx.x;
    if (idx < (size_t)N_NODES * D_HID)
        g_agg[idx] = fmaxf(g_agg[idx], 0.0f);
}

// ---------------- launch ----------------
extern "C" void kernel_launch(void* const* d_in, const int* in_sizes, int n_in,
                              void* d_out, int out_size) {
    const float* x  = (const float*)d_in[0];
    const int*   ei = (const int*)d_in[1];     // int32! (JAX x64 disabled)
    const float* W1 = (const float*)d_in[2];
    const float* b1 = (const float*)d_in[3];
    const float* W2 = (const float*)d_in[4];
    const float* b2 = (const float*)d_in[5];
    float* out = (float*)d_out;

    // 1) degrees + dinv
    k_deg_init<<<(N_NODES + 255) / 256, 256>>>();
    k_deg_edges<<<(N_EDGES + 255) / 256, 256>>>(ei);
    k_dinv<<<(N_NODES + 255) / 256, 256>>>();

    // 2) layer 1 GEMM: g_h = x @ W1
    {
        dim3 grid(D_HID / 64, (N_NODES + 63) / 64);
        k_sgemm_l1<<<grid, 256>>>(x, W1);
    }
    // 3) aggregate layer 1: init (self-loop + bias), scatter edges, relu
    {
        size_t total = (size_t)N_NODES * D_HID;
        k_self_init_l1<<<(int)((total + 255) / 256), 256>>>(b1);
        k_scatter_l1<<<(N_EDGES * 32 + 255) / 256, 256>>>(ei);
        k_relu<<<(int)((total + 255) / 256), 256>>>();
    }
    // 4) layer 2 GEMM: g_h2 = g_agg @ W2
    {
        dim3 grid(D_OUT / 64, (N_NODES + 63) / 64);
        k_sgemm_l2<<<grid, 256>>>(W2);
    }
    // 5) aggregate layer 2 directly into d_out (bias folded into init)
    {
        size_t total = (size_t)N_NODES * D_OUT;
        k_self_init_l2<<<(int)((total + 255) / 256), 256>>>(b2, out);
        k_scatter_l2<<<(N_EDGES * 32 + 255) / 256, 256>>>(ei, out);
    }
}

// round 7
// speedup vs baseline: 1.4038x; 1.4038x over previous
#include <cuda_runtime.h>
#include <cstdint>

#define N_NODES 50000
#define N_EDGES 400000
#define D_IN    512
#define D_HID   512
#define D_OUT   256

// ---------------- scratch (device globals; ONLY referenced from device code) ----------------
__device__ float g_h  [(size_t)N_NODES * D_HID];  // x@W1 (raw)
__device__ float g_agg[(size_t)N_NODES * D_HID];  // layer-1 aggregate
__device__ float g_h2 [(size_t)N_NODES * D_OUT];  // agg@W2 (raw)
__device__ float g_deg [N_NODES];
__device__ float g_dinv[N_NODES];

// ---------------- degree / norm ----------------
__global__ void k_deg_init() {
    int i = blockIdx.x * blockDim.x + threadIdx.x;
    if (i < N_NODES) g_deg[i] = 1.0f;
}
__global__ void k_deg_edges(const int* __restrict__ ei) {
    int e = blockIdx.x * blockDim.x + threadIdx.x;
    if (e < N_EDGES) atomicAdd(&g_deg[ei[N_EDGES + e]], 1.0f);
}
__global__ void k_dinv() {
    int i = blockIdx.x * blockDim.x + threadIdx.x;
    if (i < N_NODES) g_dinv[i] = rsqrtf(g_deg[i]);
}

// ---------------- fused GEMM body: C = A@B (raw), C2 = C*dinv[row]^2 + bias ----------------
// 128x128 tile, BK=16, 256 threads, 8x8 per thread, float4 global IO,
// register prefetch of the next K-slice.
template <int N, int K>
__device__ __forceinline__
void gemm_fused_body(const float* __restrict__ A, const float* __restrict__ B,
                     const float* __restrict__ bias,
                     float* __restrict__ C, float* __restrict__ C2,
                     const float* __restrict__ dinv) {
    constexpr int BM = 128, BN = 128, BK = 16;
    __shared__ float As[BK][BM];
    __shared__ float Bs[BK][BN];

    const int tid = threadIdx.x;
    const int rowBase = blockIdx.y * BM;
    const int colBase = blockIdx.x * BN;
    const int tm = tid >> 4;        // 0..15
    const int tn = tid & 15;        // 0..15

    const int aRow = tid >> 2;          // 0..63  (and +64)
    const int aK   = (tid & 3) << 2;    // 0,4,8,12
    const int bRow = tid >> 5;          // 0..7   (and +8)
    const int bCol = (tid & 31) << 2;   // 0..124

    const int gmA0 = rowBase + aRow;
    const int gmA1 = rowBase + aRow + 64;

    float4 pa0, pa1, pb0, pb1;
    const float4 z4 = make_float4(0.f, 0.f, 0.f, 0.f);

    pa0 = (gmA0 < N_NODES) ? *(const float4*)(A + (size_t)gmA0 * K + aK) : z4;
    pa1 = (gmA1 < N_NODES) ? *(const float4*)(A + (size_t)gmA1 * K + aK) : z4;
    pb0 = *(const float4*)(B + (size_t)bRow * N + colBase + bCol);
    pb1 = *(const float4*)(B + (size_t)(bRow + 8) * N + colBase + bCol);

    float acc[8][8] = {};

    for (int k0 = 0; k0 < K; k0 += BK) {
        As[aK + 0][aRow] = pa0.x; As[aK + 1][aRow] = pa0.y;
        As[aK + 2][aRow] = pa0.z; As[aK + 3][aRow] = pa0.w;
        As[aK + 0][aRow + 64] = pa1.x; As[aK + 1][aRow + 64] = pa1.y;
        As[aK + 2][aRow + 64] = pa1.z; As[aK + 3][aRow + 64] = pa1.w;
        *(float4*)&Bs[bRow][bCol]     = pb0;
        *(float4*)&Bs[bRow + 8][bCol] = pb1;
        __syncthreads();

        if (k0 + BK < K) {
            const int kn = k0 + BK;
            pa0 = (gmA0 < N_NODES) ? *(const float4*)(A + (size_t)gmA0 * K + kn + aK) : z4;
            pa1 = (gmA1 < N_NODES) ? *(const float4*)(A + (size_t)gmA1 * K + kn + aK) : z4;
            pb0 = *(const float4*)(B + (size_t)(kn + bRow) * N + colBase + bCol);
            pb1 = *(const float4*)(B + (size_t)(kn + bRow + 8) * N + colBase + bCol);
        }

        #pragma unroll
        for (int kk = 0; kk < BK; kk++) {
            float a[8], b[8];
            *(float4*)&a[0] = *(const float4*)&As[kk][tm * 8];
            *(float4*)&a[4] = *(const float4*)&As[kk][tm * 8 + 4];
            *(float4*)&b[0] = *(const float4*)&Bs[kk][tn * 8];
            *(float4*)&b[4] = *(const float4*)&Bs[kk][tn * 8 + 4];
            #pragma unroll
            for (int i = 0; i < 8; i++)
                #pragma unroll
                for (int j = 0; j < 8; j++)
                    acc[i][j] = fmaf(a[i], b[j], acc[i][j]);
        }
        __syncthreads();
    }

    float bv[8];
    *(float4*)&bv[0] = *(const float4*)(bias + colBase + tn * 8);
    *(float4*)&bv[4] = *(const float4*)(bias + colBase + tn * 8 + 4);

    #pragma unroll
    for (int i = 0; i < 8; i++) {
        int gm = rowBase + tm * 8 + i;
        if (gm < N_NODES) {
            float s  = dinv[gm];
            float ss = s * s;
            float* crow  = C  + (size_t)gm * N + colBase + tn * 8;
            float* c2row = C2 + (size_t)gm * N + colBase + tn * 8;
            float4 v0 = make_float4(acc[i][0], acc[i][1], acc[i][2], acc[i][3]);
            float4 v1 = make_float4(acc[i][4], acc[i][5], acc[i][6], acc[i][7]);
            *(float4*)crow       = v0;
            *(float4*)(crow + 4) = v1;
            float4 w0 = make_float4(fmaf(v0.x, ss, bv[0]), fmaf(v0.y, ss, bv[1]),
                                    fmaf(v0.z, ss, bv[2]), fmaf(v0.w, ss, bv[3]));
            float4 w1 = make_float4(fmaf(v1.x, ss, bv[4]), fmaf(v1.y, ss, bv[5]),
                                    fmaf(v1.z, ss, bv[6]), fmaf(v1.w, ss, bv[7]));
            *(float4*)c2row       = w0;
            *(float4*)(c2row + 4) = w1;
        }
    }
}

// wrappers: globals decay to device pointers HERE, inside device code (legal)
__global__ __launch_bounds__(256)
void k_gemm_l1(const float* __restrict__ x, const float* __restrict__ W1,
               const float* __restrict__ b1) {
    gemm_fused_body<D_HID, D_IN>(x, W1, b1, g_h, g_agg, g_dinv);
}
__global__ __launch_bounds__(256)
void k_gemm_l2(const float* __restrict__ W2, const float* __restrict__ b2,
               float* __restrict__ out) {
    gemm_fused_body<D_OUT, D_HID>(g_agg, W2, b2, g_h2, out, g_dinv);
}

// ---------------- edge scatter: dst[d,:] += h[s,:] * dinv[s]*dinv[d] ----------------
// float4 gather + scalar atomic adds (proven). Globals bound inside wrappers.
template <int D>
__device__ __forceinline__
void scatter_body(const int* __restrict__ ei, const float* __restrict__ h,
                  float* __restrict__ dst, const float* __restrict__ dinv) {
    int warp = blockIdx.x * (blockDim.x >> 5) + (threadIdx.x >> 5);
    int lane = threadIdx.x & 31;
    if (warp >= N_EDGES) return;
    int s = ei[warp];
    int d = ei[N_EDGES + warp];
    float w = dinv[s] * dinv[d];
    const float4* __restrict__ hs4 = (const float4*)(h + (size_t)s * D);
    float* ad = dst + (size_t)d * D;
    #pragma unroll
    for (int c4 = lane; c4 < D / 4; c4 += 32) {
        float4 v = hs4[c4];
        float* p = ad + c4 * 4;
        atomicAdd(p + 0, v.x * w);
        atomicAdd(p + 1, v.y * w);
        atomicAdd(p + 2, v.z * w);
        atomicAdd(p + 3, v.w * w);
    }
}
__global__ __launch_bounds__(256)
void k_scatter_l1(const int* __restrict__ ei) {
    scatter_body<D_HID>(ei, g_h, g_agg, g_dinv);
}
__global__ __launch_bounds__(256)
void k_scatter_l2(const int* __restrict__ ei, float* __restrict__ out) {
    scatter_body<D_OUT>(ei, g_h2, out, g_dinv);
}

// ---------------- in-place relu on g_agg (vectorized) ----------------
__global__ void k_relu() {
    size_t idx = (size_t)blockIdx.x * blockDim.x + threadIdx.x;
    size_t total4 = (size_t)N_NODES * D_HID / 4;
    if (idx < total4) {
        float4 v = ((float4*)g_agg)[idx];
        v.x = fmaxf(v.x, 0.f); v.y = fmaxf(v.y, 0.f);
        v.z = fmaxf(v.z, 0.f); v.w = fmaxf(v.w, 0.f);
        ((float4*)g_agg)[idx] = v;
    }
}

// ---------------- launch (NO device-global symbols referenced from host!) ----------------
extern "C" void kernel_launch(void* const* d_in, const int* in_sizes, int n_in,
                              void* d_out, int out_size) {
    const float* x  = (const float*)d_in[0];
    const int*   ei = (const int*)d_in[1];     // int32 (JAX x64 disabled)
    const float* W1 = (const float*)d_in[2];
    const float* b1 = (const float*)d_in[3];
    const float* W2 = (const float*)d_in[4];
    const float* b2 = (const float*)d_in[5];
    float* out = (float*)d_out;

    // 1) degrees + dinv (precedes GEMM1's fused epilogue)
    k_deg_init<<<(N_NODES + 255) / 256, 256>>>();
    k_deg_edges<<<(N_EDGES + 255) / 256, 256>>>(ei);
    k_dinv<<<(N_NODES + 255) / 256, 256>>>();

    // 2) layer 1: g_h = x@W1 (raw), g_agg = g_h*dinv^2 + b1 (fused epilogue)
    {
        dim3 grid(D_HID / 128, (N_NODES + 127) / 128);
        k_gemm_l1<<<grid, 256>>>(x, W1, b1);
    }
    // 3) scatter edges into g_agg, then relu
    k_scatter_l1<<<(N_EDGES + 7) / 8, 256>>>(ei);
    {
        size_t total4 = (size_t)N_NODES * D_HID / 4;
        k_relu<<<(int)((total4 + 255) / 256), 256>>>();
    }
    // 4) layer 2: g_h2 = g_agg@W2 (raw), out = g_h2*dinv^2 + b2 (fused epilogue)
    {
        dim3 grid(D_OUT / 128, (N_NODES + 127) / 128);
        k_gemm_l2<<<grid, 256>>>(W2, b2, out);
    }
    // 5) scatter edges into out
    k_scatter_l2<<<(N_EDGES + 7) / 8, 256>>>(ei, out);
}

// round 8
// speedup vs baseline: 1.7049x; 1.2145x over previous
#include <cuda_runtime.h>
#include <cuda_fp16.h>
#include <cstdint>

#define N_NODES 50000
#define N_EDGES 400000
#define D_IN    512
#define D_HID   512
#define D_OUT   256
#define KP      1536   // packed K' = 3 * 512

// ---------------- scratch (device globals; ONLY referenced from device code) ----------------
__device__ float  g_h  [(size_t)N_NODES * D_HID];  // layer GEMM raw output (fp32)
__device__ float  g_agg[(size_t)N_NODES * D_HID];  // layer-1 aggregate
__device__ float  g_h2 [(size_t)N_NODES * D_OUT];  // layer-2 raw output
__device__ float  g_deg [N_NODES];
__device__ float  g_dinv[N_NODES];
__device__ __half g_Ah [(size_t)N_NODES * KP];     // packed A'' = [hi | lo | hi]
__device__ __half g_BhT[(size_t)D_HID * KP];       // packed B''^T, n-major: [n][k']

// ---------------- degree / norm ----------------
__global__ void k_deg_init() {
    int i = blockIdx.x * blockDim.x + threadIdx.x;
    if (i < N_NODES) g_deg[i] = 1.0f;
}
__global__ void k_deg_edges(const int* __restrict__ ei) {
    int e = blockIdx.x * blockDim.x + threadIdx.x;
    if (e < N_EDGES) atomicAdd(&g_deg[ei[N_EDGES + e]], 1.0f);
}
__global__ void k_dinv() {
    int i = blockIdx.x * blockDim.x + threadIdx.x;
    if (i < N_NODES) g_dinv[i] = rsqrtf(g_deg[i]);
}

// ---------------- packing: A'' = [hi | lo | hi], optionally relu(src) ----------------
template <int DO_RELU>
__device__ __forceinline__
void packA_body(const float* __restrict__ src, __half* __restrict__ dst) {
    size_t idx = (size_t)blockIdx.x * blockDim.x + threadIdx.x;
    if (idx < (size_t)N_NODES * 512) {
        size_t m = idx >> 9;
        int    k = (int)(idx & 511);
        float v = src[idx];
        if (DO_RELU) v = fmaxf(v, 0.0f);
        __half hi = __float2half(v);
        __half lo = __float2half(v - __half2float(hi));
        __half* row = dst + m * KP;
        row[k]        = hi;
        row[512 + k]  = lo;
        row[1024 + k] = hi;
    }
}
__global__ void k_pack_x(const float* __restrict__ x)  { packA_body<0>(x, g_Ah); }
__global__ void k_pack_agg()                           { packA_body<1>(g_agg, g_Ah); }

// B''^T n-major: rows of B'' are [Bhi ; Bhi ; Blo]; store at [n][k']
template <int N>
__device__ __forceinline__
void packB_body(const float* __restrict__ W, __half* __restrict__ dst) {
    int idx = blockIdx.x * blockDim.x + threadIdx.x;
    if (idx < 512 * N) {
        int k = idx / N, n = idx % N;
        float v = W[idx];
        __half hi = __float2half(v);
        __half lo = __float2half(v - __half2float(hi));
        __half* col = dst + (size_t)n * KP;
        col[k]        = hi;
        col[512 + k]  = hi;
        col[1024 + k] = lo;
    }
}
__global__ void k_pack_W1(const float* __restrict__ W) { packB_body<D_HID>(W, g_BhT); }
__global__ void k_pack_W2(const float* __restrict__ W) { packB_body<D_OUT>(W, g_BhT); }

// ---------------- mma.sync m16n8k16 helper ----------------
__device__ __forceinline__
void mma16816(float* d, const uint32_t* a, const uint32_t* b) {
    asm volatile(
        "mma.sync.aligned.m16n8k16.row.col.f32.f16.f16.f32 "
        "{%0,%1,%2,%3}, {%4,%5,%6,%7}, {%8,%9}, {%0,%1,%2,%3};\n"
        : "+f"(d[0]), "+f"(d[1]), "+f"(d[2]), "+f"(d[3])
        : "r"(a[0]), "r"(a[1]), "r"(a[2]), "r"(a[3]),
          "r"(b[0]), "r"(b[1]));
}

// ---------------- tensor-core GEMM: C[M,N] = A''[M,KP] @ B''[KP,N] ----------------
// 128x128 block tile, BK=32, 256 threads (8 warps, 2x4), warp tile 64x32,
// double-buffered smem, fused dual-output epilogue.
template <int N>
__device__ __forceinline__
void gemm_mma_body(const __half* __restrict__ Ah, const __half* __restrict__ BhT,
                   const float* __restrict__ bias,
                   float* __restrict__ C, float* __restrict__ C2,
                   const float* __restrict__ dinv) {
    constexpr int BM = 128, BK = 32, PITCH = 40;
    __shared__ __half As[2][BM][PITCH];
    __shared__ __half Bs[2][BM][PITCH];

    const int tid  = threadIdx.x;
    const int lane = tid & 31;
    const int wid  = tid >> 5;
    const int warp_m = wid >> 2;       // 0..1
    const int warp_n = wid & 3;        // 0..3
    const int rowBase = blockIdx.y * BM;
    const int colBase = blockIdx.x * BM;

    const int lg  = lane >> 2;          // 0..7
    const int lc2 = (lane & 3) * 2;     // 0,2,4,6

    // staging assignment: 512 uint4 per operand tile, 2 per thread
    const int r0 = tid >> 2,  s0 = (tid & 3) * 8;
    const int r1 = r0 + 64;   // (tid+256)>>2
    const uint4 z4 = make_uint4(0, 0, 0, 0);

    float acc[4][4][4];
    #pragma unroll
    for (int i = 0; i < 4; i++)
        #pragma unroll
        for (int j = 0; j < 4; j++)
            #pragma unroll
            for (int q = 0; q < 4; q++) acc[i][j][q] = 0.0f;

    // prologue: load tile 0 into buffer 0
    uint4 na0, na1, nb0, nb1;
    {
        int gm0 = rowBase + r0, gm1 = rowBase + r1;
        na0 = (gm0 < N_NODES) ? *(const uint4*)(Ah + (size_t)gm0 * KP + s0) : z4;
        na1 = (gm1 < N_NODES) ? *(const uint4*)(Ah + (size_t)gm1 * KP + s0) : z4;
        nb0 = *(const uint4*)(BhT + (size_t)(colBase + r0) * KP + s0);
        nb1 = *(const uint4*)(BhT + (size_t)(colBase + r1) * KP + s0);
        *(uint4*)&As[0][r0][s0] = na0;
        *(uint4*)&As[0][r1][s0] = na1;
        *(uint4*)&Bs[0][r0][s0] = nb0;
        *(uint4*)&Bs[0][r1][s0] = nb1;
    }
    __syncthreads();

    constexpr int NIT = KP / BK;   // 48
    for (int t = 0; t < NIT; t++) {
        const int buf = t & 1;

        if (t + 1 < NIT) {
            const int k0 = (t + 1) * BK;
            int gm0 = rowBase + r0, gm1 = rowBase + r1;
            na0 = (gm0 < N_NODES) ? *(const uint4*)(Ah + (size_t)gm0 * KP + k0 + s0) : z4;
            na1 = (gm1 < N_NODES) ? *(const uint4*)(Ah + (size_t)gm1 * KP + k0 + s0) : z4;
            nb0 = *(const uint4*)(BhT + (size_t)(colBase + r0) * KP + k0 + s0);
            nb1 = *(const uint4*)(BhT + (size_t)(colBase + r1) * KP + k0 + s0);
        }

        #pragma unroll
        for (int ks = 0; ks < 2; ks++) {
            const int c = ks * 16 + lc2;
            uint32_t afr[4][4], bfr[4][2];
            #pragma unroll
            for (int mf = 0; mf < 4; mf++) {
                int r = warp_m * 64 + mf * 16 + lg;
                afr[mf][0] = *(const uint32_t*)&As[buf][r][c];
                afr[mf][1] = *(const uint32_t*)&As[buf][r + 8][c];
                afr[mf][2] = *(const uint32_t*)&As[buf][r][c + 8];
                afr[mf][3] = *(const uint32_t*)&As[buf][r + 8][c + 8];
            }
            #pragma unroll
            for (int nf = 0; nf < 4; nf++) {
                int n = warp_n * 32 + nf * 8 + lg;
                bfr[nf][0] = *(const uint32_t*)&Bs[buf][n][c];
                bfr[nf][1] = *(const uint32_t*)&Bs[buf][n][c + 8];
            }
            #pragma unroll
            for (int mf = 0; mf < 4; mf++)
                #pragma unroll
                for (int nf = 0; nf < 4; nf++)
                    mma16816(acc[mf][nf], afr[mf], bfr[nf]);
        }

        if (t + 1 < NIT) {
            const int nbuf = buf ^ 1;
            *(uint4*)&As[nbuf][r0][s0] = na0;
            *(uint4*)&As[nbuf][r1][s0] = na1;
            *(uint4*)&Bs[nbuf][r0][s0] = nb0;
            *(uint4*)&Bs[nbuf][r1][s0] = nb1;
        }
        __syncthreads();
    }

    // epilogue: raw C + fused self-loop/bias into C2
    #pragma unroll
    for (int mf = 0; mf < 4; mf++) {
        #pragma unroll
        for (int hh = 0; hh < 2; hh++) {
            int m = rowBase + warp_m * 64 + mf * 16 + lg + hh * 8;
            if (m < N_NODES) {
                float s  = dinv[m];
                float ss = s * s;
                #pragma unroll
                for (int nf = 0; nf < 4; nf++) {
                    int n = colBase + warp_n * 32 + nf * 8 + lc2;
                    float d0 = acc[mf][nf][hh * 2 + 0];
                    float d1 = acc[mf][nf][hh * 2 + 1];
                    *(float2*)(C + (size_t)m * N + n) = make_float2(d0, d1);
                    float b0 = bias[n], b1 = bias[n + 1];
                    *(float2*)(C2 + (size_t)m * N + n) =
                        make_float2(fmaf(d0, ss, b0), fmaf(d1, ss, b1));
                }
            }
        }
    }
}

__global__ __launch_bounds__(256)
void k_mma_l1(const float* __restrict__ b1) {
    gemm_mma_body<D_HID>(g_Ah, g_BhT, b1, g_h, g_agg, g_dinv);
}
__global__ __launch_bounds__(256)
void k_mma_l2(const float* __restrict__ b2, float* __restrict__ out) {
    gemm_mma_body<D_OUT>(g_Ah, g_BhT, b2, g_h2, out, g_dinv);
}

// ---------------- edge scatter (R7-proven): float4 gather + scalar atomics ----------------
template <int D>
__device__ __forceinline__
void scatter_body(const int* __restrict__ ei, const float* __restrict__ h,
                  float* __restrict__ dst, const float* __restrict__ dinv) {
    int warp = blockIdx.x * (blockDim.x >> 5) + (threadIdx.x >> 5);
    int lane = threadIdx.x & 31;
    if (warp >= N_EDGES) return;
    int s = ei[warp];
    int d = ei[N_EDGES + warp];
    float w = dinv[s] * dinv[d];
    const float4* __restrict__ hs4 = (const float4*)(h + (size_t)s * D);
    float* ad = dst + (size_t)d * D;
    #pragma unroll
    for (int c4 = lane; c4 < D / 4; c4 += 32) {
        float4 v = hs4[c4];
        float* p = ad + c4 * 4;
        atomicAdd(p + 0, v.x * w);
        atomicAdd(p + 1, v.y * w);
        atomicAdd(p + 2, v.z * w);
        atomicAdd(p + 3, v.w * w);
    }
}
__global__ __launch_bounds__(256)
void k_scatter_l1(const int* __restrict__ ei) {
    scatter_body<D_HID>(ei, g_h, g_agg, g_dinv);
}
__global__ __launch_bounds__(256)
void k_scatter_l2(const int* __restrict__ ei, float* __restrict__ out) {
    scatter_body<D_OUT>(ei, g_h2, out, g_dinv);
}

// ---------------- launch ----------------
extern "C" void kernel_launch(void* const* d_in, const int* in_sizes, int n_in,
                              void* d_out, int out_size) {
    const float* x  = (const float*)d_in[0];
    const int*   ei = (const int*)d_in[1];     // int32 (JAX x64 disabled)
    const float* W1 = (const float*)d_in[2];
    const float* b1 = (const float*)d_in[3];
    const float* W2 = (const float*)d_in[4];
    const float* b2 = (const float*)d_in[5];
    float* out = (float*)d_out;

    // 1) degrees + dinv
    k_deg_init<<<(N_NODES + 255) / 256, 256>>>();
    k_deg_edges<<<(N_EDGES + 255) / 256, 256>>>(ei);
    k_dinv<<<(N_NODES + 255) / 256, 256>>>();

    // 2) pack layer-1 operands
    {
        size_t tot = (size_t)N_NODES * 512;
        k_pack_x<<<(int)((tot + 255) / 256), 256>>>(x);
        k_pack_W1<<<(512 * D_HID + 255) / 256, 256>>>(W1);
    }
    // 3) layer 1 tensor GEMM: g_h raw, g_agg = self+bias (fused)
    {
        dim3 grid(D_HID / 128, (N_NODES + 127) / 128);
        k_mma_l1<<<grid, 256>>>(b1);
    }
    // 4) scatter edges into g_agg
    k_scatter_l1<<<(N_EDGES + 7) / 8, 256>>>(ei);

    // 5) pack layer-2 operands (relu fused into A-pack)
    {
        size_t tot = (size_t)N_NODES * 512;
        k_pack_agg<<<(int)((tot + 255) / 256), 256>>>();
        k_pack_W2<<<(512 * D_OUT + 255) / 256, 256>>>(W2);
    }
    // 6) layer 2 tensor GEMM: g_h2 raw, out = self+bias (fused)
    {
        dim3 grid(D_OUT / 128, (N_NODES + 127) / 128);
        k_mma_l2<<<grid, 256>>>(b2, out);
    }
    // 7) scatter edges into out
    k_scatter_l2<<<(N_EDGES + 7) / 8, 256>>>(ei, out);
}

// round 9
// speedup vs baseline: 3.6815x; 2.1594x over previous
#include <cuda_runtime.h>
#include <cuda_fp16.h>
#include <cstdint>

#define N_NODES 50000
#define N_EDGES 400000
#define D_IN    512
#define D_HID   512
#define D_OUT   256
#define KP      1024   // packed K' = 2 * 512 (hi | lo split of A; B uses hi twice)

// ---------------- scratch (device globals; referenced ONLY from device code) ----------------
__device__ float  g_h   [(size_t)N_NODES * D_HID];  // layer GEMM raw output (fp32)
__device__ float  g_agg [(size_t)N_NODES * D_HID];  // layer-1 aggregate (post-relu)
__device__ float  g_h2  [(size_t)N_NODES * D_OUT];  // layer-2 raw output
__device__ float  g_dinv[N_NODES];
__device__ __half g_Ah  [(size_t)N_NODES * KP];     // packed A'' = [hi | lo]
__device__ __half g_BhT [(size_t)D_HID * KP];       // packed B''^T n-major: [n][hi|hi]
__device__ int    g_cnt [N_NODES];                  // in-degree (excl self)
__device__ int    g_row [N_NODES + 1];              // CSR row starts
__device__ int    g_fill[N_NODES];                  // fill cursors
__device__ int    g_csrc[N_EDGES];                  // CSR src ids
__device__ float  g_cw  [N_EDGES];                  // CSR edge weights

// ---------------- degree count / norm ----------------
__global__ void k_cnt_zero() {
    int i = blockIdx.x * blockDim.x + threadIdx.x;
    if (i < N_NODES) g_cnt[i] = 0;
}
__global__ void k_count(const int* __restrict__ ei) {
    int e = blockIdx.x * blockDim.x + threadIdx.x;
    if (e < N_EDGES) atomicAdd(&g_cnt[ei[N_EDGES + e]], 1);
}
__global__ void k_dinv() {
    int i = blockIdx.x * blockDim.x + threadIdx.x;
    if (i < N_NODES) g_dinv[i] = rsqrtf(1.0f + (float)g_cnt[i]);  // +1 self-loop
}

// ---------------- exclusive scan over g_cnt (single block, 1024 threads) ----------------
#define SCAN_CHUNK 49   // 1024*49 = 50176 >= 50000
__global__ __launch_bounds__(1024)
void k_scan() {
    __shared__ int sm[1024];
    int tid = threadIdx.x;
    int base = tid * SCAN_CHUNK;
    int local = 0;
    #pragma unroll
    for (int i = 0; i < SCAN_CHUNK; i++) {
        int idx = base + i;
        if (idx < N_NODES) local += g_cnt[idx];
    }
    sm[tid] = local;
    __syncthreads();
    // Hillis-Steele inclusive scan
    for (int off = 1; off < 1024; off <<= 1) {
        int v = (tid >= off) ? sm[tid - off] : 0;
        __syncthreads();
        sm[tid] += v;
        __syncthreads();
    }
    int run = (tid == 0) ? 0 : sm[tid - 1];
    #pragma unroll
    for (int i = 0; i < SCAN_CHUNK; i++) {
        int idx = base + i;
        if (idx < N_NODES) {
            g_row[idx]  = run;
            g_fill[idx] = run;
            run += g_cnt[idx];
        }
    }
    if (tid == 1023) g_row[N_NODES] = sm[1023];
}

__global__ void k_fill(const int* __restrict__ ei) {
    int e = blockIdx.x * blockDim.x + threadIdx.x;
    if (e < N_EDGES) {
        int s = ei[e];
        int d = ei[N_EDGES + e];
        int pos = atomicAdd(&g_fill[d], 1);
        g_csrc[pos] = s;
        g_cw[pos]   = g_dinv[s] * g_dinv[d];
    }
}

// ---------------- packing ----------------
// A'' = [hi | lo] per row (vectorized: 4 cols per thread)
__device__ __forceinline__
void packA_body(const float* __restrict__ src, __half* __restrict__ dst) {
    size_t idx = (size_t)blockIdx.x * blockDim.x + threadIdx.x;
    if (idx < (size_t)N_NODES * 128) {
        size_t m = idx >> 7;
        int c4 = (int)(idx & 127) * 4;
        float4 v = *(const float4*)(src + m * 512 + c4);
        __half hx = __float2half(v.x), hy = __float2half(v.y);
        __half hz = __float2half(v.z), hw = __float2half(v.w);
        __half lx = __float2half(v.x - __half2float(hx));
        __half ly = __float2half(v.y - __half2float(hy));
        __half lz = __float2half(v.z - __half2float(hz));
        __half lw = __float2half(v.w - __half2float(hw));
        __half* row = dst + m * KP;
        *(__half2*)(row + c4)           = __halves2half2(hx, hy);
        *(__half2*)(row + c4 + 2)       = __halves2half2(hz, hw);
        *(__half2*)(row + 512 + c4)     = __halves2half2(lx, ly);
        *(__half2*)(row + 512 + c4 + 2) = __halves2half2(lz, lw);
    }
}
__global__ void k_pack_x(const float* __restrict__ x) { packA_body(x, g_Ah); }
__global__ void k_pack_agg()                          { packA_body(g_agg, g_Ah); }

// B''^T n-major: both K' segments hold Bhi
template <int N>
__device__ __forceinline__
void packB_body(const float* __restrict__ W, __half* __restrict__ dst) {
    int idx = blockIdx.x * blockDim.x + threadIdx.x;
    if (idx < 512 * N) {
        int k = idx / N, n = idx % N;
        __half hi = __float2half(W[idx]);
        __half* col = dst + (size_t)n * KP;
        col[k]       = hi;
        col[512 + k] = hi;
    }
}
__global__ void k_pack_W1(const float* __restrict__ W) { packB_body<D_HID>(W, g_BhT); }
__global__ void k_pack_W2(const float* __restrict__ W) { packB_body<D_OUT>(W, g_BhT); }

// ---------------- mma.sync m16n8k16 ----------------
__device__ __forceinline__
void mma16816(float* d, const uint32_t* a, const uint32_t* b) {
    asm volatile(
        "mma.sync.aligned.m16n8k16.row.col.f32.f16.f16.f32 "
        "{%0,%1,%2,%3}, {%4,%5,%6,%7}, {%8,%9}, {%0,%1,%2,%3};\n"
        : "+f"(d[0]), "+f"(d[1]), "+f"(d[2]), "+f"(d[3])
        : "r"(a[0]), "r"(a[1]), "r"(a[2]), "r"(a[3]),
          "r"(b[0]), "r"(b[1]));
}

// ---------------- tensor-core GEMM: C[M,N] = A''[M,KP] @ B''[KP,N] (raw only) ----------------
template <int N>
__device__ __forceinline__
void gemm_mma_body(const __half* __restrict__ Ah, const __half* __restrict__ BhT,
                   float* __restrict__ C) {
    constexpr int BM = 128, BK = 32, PITCH = 40;
    __shared__ __half As[2][BM][PITCH];
    __shared__ __half Bs[2][BM][PITCH];

    const int tid  = threadIdx.x;
    const int lane = tid & 31;
    const int wid  = tid >> 5;
    const int warp_m = wid >> 2;       // 0..1
    const int warp_n = wid & 3;        // 0..3
    const int rowBase = blockIdx.y * BM;
    const int colBase = blockIdx.x * BM;

    const int lg  = lane >> 2;          // 0..7
    const int lc2 = (lane & 3) * 2;     // 0,2,4,6

    const int r0 = tid >> 2,  s0 = (tid & 3) * 8;
    const int r1 = r0 + 64;
    const uint4 z4 = make_uint4(0, 0, 0, 0);

    float acc[4][4][4];
    #pragma unroll
    for (int i = 0; i < 4; i++)
        #pragma unroll
        for (int j = 0; j < 4; j++)
            #pragma unroll
            for (int q = 0; q < 4; q++) acc[i][j][q] = 0.0f;

    uint4 na0, na1, nb0, nb1;
    {
        int gm0 = rowBase + r0, gm1 = rowBase + r1;
        na0 = (gm0 < N_NODES) ? *(const uint4*)(Ah + (size_t)gm0 * KP + s0) : z4;
        na1 = (gm1 < N_NODES) ? *(const uint4*)(Ah + (size_t)gm1 * KP + s0) : z4;
        nb0 = *(const uint4*)(BhT + (size_t)(colBase + r0) * KP + s0);
        nb1 = *(const uint4*)(BhT + (size_t)(colBase + r1) * KP + s0);
        *(uint4*)&As[0][r0][s0] = na0;
        *(uint4*)&As[0][r1][s0] = na1;
        *(uint4*)&Bs[0][r0][s0] = nb0;
        *(uint4*)&Bs[0][r1][s0] = nb1;
    }
    __syncthreads();

    constexpr int NIT = KP / BK;   // 32
    for (int t = 0; t < NIT; t++) {
        const int buf = t & 1;

        if (t + 1 < NIT) {
            const int k0 = (t + 1) * BK;
            int gm0 = rowBase + r0, gm1 = rowBase + r1;
            na0 = (gm0 < N_NODES) ? *(const uint4*)(Ah + (size_t)gm0 * KP + k0 + s0) : z4;
            na1 = (gm1 < N_NODES) ? *(const uint4*)(Ah + (size_t)gm1 * KP + k0 + s0) : z4;
            nb0 = *(const uint4*)(BhT + (size_t)(colBase + r0) * KP + k0 + s0);
            nb1 = *(const uint4*)(BhT + (size_t)(colBase + r1) * KP + k0 + s0);
        }

        #pragma unroll
        for (int ks = 0; ks < 2; ks++) {
            const int c = ks * 16 + lc2;
            uint32_t afr[4][4], bfr[4][2];
            #pragma unroll
            for (int mf = 0; mf < 4; mf++) {
                int r = warp_m * 64 + mf * 16 + lg;
                afr[mf][0] = *(const uint32_t*)&As[buf][r][c];
                afr[mf][1] = *(const uint32_t*)&As[buf][r + 8][c];
                afr[mf][2] = *(const uint32_t*)&As[buf][r][c + 8];
                afr[mf][3] = *(const uint32_t*)&As[buf][r + 8][c + 8];
            }
            #pragma unroll
            for (int nf = 0; nf < 4; nf++) {
                int n = warp_n * 32 + nf * 8 + lg;
                bfr[nf][0] = *(const uint32_t*)&Bs[buf][n][c];
                bfr[nf][1] = *(const uint32_t*)&Bs[buf][n][c + 8];
            }
            #pragma unroll
            for (int mf = 0; mf < 4; mf++)
                #pragma unroll
                for (int nf = 0; nf < 4; nf++)
                    mma16816(acc[mf][nf], afr[mf], bfr[nf]);
        }

        if (t + 1 < NIT) {
            const int nbuf = buf ^ 1;
            *(uint4*)&As[nbuf][r0][s0] = na0;
            *(uint4*)&As[nbuf][r1][s0] = na1;
            *(uint4*)&Bs[nbuf][r0][s0] = nb0;
            *(uint4*)&Bs[nbuf][r1][s0] = nb1;
        }
        __syncthreads();
    }

    #pragma unroll
    for (int mf = 0; mf < 4; mf++) {
        #pragma unroll
        for (int hh = 0; hh < 2; hh++) {
            int m = rowBase + warp_m * 64 + mf * 16 + lg + hh * 8;
            if (m < N_NODES) {
                #pragma unroll
                for (int nf = 0; nf < 4; nf++) {
                    int n = colBase + warp_n * 32 + nf * 8 + lc2;
                    *(float2*)(C + (size_t)m * N + n) =
                        make_float2(acc[mf][nf][hh * 2 + 0], acc[mf][nf][hh * 2 + 1]);
                }
            }
        }
    }
}

__global__ __launch_bounds__(256)
void k_mma_l1() { gemm_mma_body<D_HID>(g_Ah, g_BhT, g_h); }
__global__ __launch_bounds__(256)
void k_mma_l2() { gemm_mma_body<D_OUT>(g_Ah, g_BhT, g_h2); }

// ---------------- CSR gather: dst[i] = (relu)( h[i]*dinv^2 + b + sum_j w_j*h[src_j] ) ----------
// one block (128 threads) per node; D=512 -> float4/thread, D=256 -> float2/thread
__global__ __launch_bounds__(128)
void k_gather_l1(const float* __restrict__ b1) {
    int i = blockIdx.x;
    int col = threadIdx.x * 4;
    float s = g_dinv[i];
    float ss = s * s;
    float4 hv = *(const float4*)(g_h + (size_t)i * D_HID + col);
    float4 bv = *(const float4*)(b1 + col);
    float4 acc = make_float4(fmaf(hv.x, ss, bv.x), fmaf(hv.y, ss, bv.y),
                             fmaf(hv.z, ss, bv.z), fmaf(hv.w, ss, bv.w));
    int beg = g_row[i], end = g_row[i + 1];
    int j = beg;
    for (; j + 1 < end; j += 2) {
        int   s0 = g_csrc[j],   s1 = g_csrc[j + 1];
        float w0 = g_cw[j],     w1 = g_cw[j + 1];
        float4 a = *(const float4*)(g_h + (size_t)s0 * D_HID + col);
        float4 b = *(const float4*)(g_h + (size_t)s1 * D_HID + col);
        acc.x = fmaf(a.x, w0, fmaf(b.x, w1, acc.x));
        acc.y = fmaf(a.y, w0, fmaf(b.y, w1, acc.y));
        acc.z = fmaf(a.z, w0, fmaf(b.z, w1, acc.z));
        acc.w = fmaf(a.w, w0, fmaf(b.w, w1, acc.w));
    }
    if (j < end) {
        int s0 = g_csrc[j]; float w0 = g_cw[j];
        float4 a = *(const float4*)(g_h + (size_t)s0 * D_HID + col);
        acc.x = fmaf(a.x, w0, acc.x); acc.y = fmaf(a.y, w0, acc.y);
        acc.z = fmaf(a.z, w0, acc.z); acc.w = fmaf(a.w, w0, acc.w);
    }
    acc.x = fmaxf(acc.x, 0.f); acc.y = fmaxf(acc.y, 0.f);
    acc.z = fmaxf(acc.z, 0.f); acc.w = fmaxf(acc.w, 0.f);
    *(float4*)(g_agg + (size_t)i * D_HID + col) = acc;
}

__global__ __launch_bounds__(128)
void k_gather_l2(const float* __restrict__ b2, float* __restrict__ out) {
    int i = blockIdx.x;
    int col = threadIdx.x * 2;
    float s = g_dinv[i];
    float ss = s * s;
    float2 hv = *(const float2*)(g_h2 + (size_t)i * D_OUT + col);
    float2 bv = *(const float2*)(b2 + col);
    float2 acc = make_float2(fmaf(hv.x, ss, bv.x), fmaf(hv.y, ss, bv.y));
    int beg = g_row[i], end = g_row[i + 1];
    int j = beg;
    for (; j + 1 < end; j += 2) {
        int   s0 = g_csrc[j],   s1 = g_csrc[j + 1];
        float w0 = g_cw[j],     w1 = g_cw[j + 1];
        float2 a = *(const float2*)(g_h2 + (size_t)s0 * D_OUT + col);
        float2 b = *(const float2*)(g_h2 + (size_t)s1 * D_OUT + col);
        acc.x = fmaf(a.x, w0, fmaf(b.x, w1, acc.x));
        acc.y = fmaf(a.y, w0, fmaf(b.y, w1, acc.y));
    }
    if (j < end) {
        int s0 = g_csrc[j]; float w0 = g_cw[j];
        float2 a = *(const float2*)(g_h2 + (size_t)s0 * D_OUT + col);
        acc.x = fmaf(a.x, w0, acc.x); acc.y = fmaf(a.y, w0, acc.y);
    }
    *(float2*)(out + (size_t)i * D_OUT + col) = acc;
}

// ---------------- launch ----------------
extern "C" void kernel_launch(void* const* d_in, const int* in_sizes, int n_in,
                              void* d_out, int out_size) {
    const float* x  = (const float*)d_in[0];
    const int*   ei = (const int*)d_in[1];     // int32 (JAX x64 disabled)
    const float* W1 = (const float*)d_in[2];
    const float* b1 = (const float*)d_in[3];
    const float* W2 = (const float*)d_in[4];
    const float* b2 = (const float*)d_in[5];
    float* out = (float*)d_out;

    // 1) degree counts, dinv, CSR build
    k_cnt_zero<<<(N_NODES + 255) / 256, 256>>>();
    k_count<<<(N_EDGES + 255) / 256, 256>>>(ei);
    k_dinv<<<(N_NODES + 255) / 256, 256>>>();
    k_scan<<<1, 1024>>>();
    k_fill<<<(N_EDGES + 255) / 256, 256>>>(ei);

    // 2) layer 1: pack, tensor GEMM (raw), CSR gather (+self+bias+relu)
    {
        size_t tot = (size_t)N_NODES * 128;
        k_pack_x<<<(int)((tot + 255) / 256), 256>>>(x);
        k_pack_W1<<<(512 * D_HID + 255) / 256, 256>>>(W1);
        dim3 grid(D_HID / 128, (N_NODES + 127) / 128);
        k_mma_l1<<<grid, 256>>>();
        k_gather_l1<<<N_NODES, 128>>>(b1);
    }
    // 3) layer 2: pack, tensor GEMM (raw), CSR gather (+self+bias) into d_out
    {
        size_t tot = (size_t)N_NODES * 128;
        k_pack_agg<<<(int)((tot + 255) / 256), 256>>>();
        k_pack_W2<<<(512 * D_OUT + 255) / 256, 256>>>(W2);
        dim3 grid(D_OUT / 128, (N_NODES + 127) / 128);
        k_mma_l2<<<grid, 256>>>();
        k_gather_l2<<<N_NODES, 128>>>(b2, out);
    }
}

// round 10
// speedup vs baseline: 4.6678x; 1.2679x over previous
#include <cuda_runtime.h>
#include <cuda_fp16.h>
#include <cstdint>

#define N_NODES 50000
#define N_EDGES 400000
#define D_IN    512
#define D_HID   512
#define D_OUT   256
#define KP      1024   // packed K' = 2*512 (A = [hi|lo]; B = [hi|hi])
#define NB      196    // scan blocks: 196*256 >= 50000

// ---------------- scratch (device globals; referenced ONLY from device code) ----------------
__device__ __half g_hh  [(size_t)N_NODES * D_HID];  // layer-1 GEMM raw output (fp16)
__device__ __half g_h2h [(size_t)N_NODES * D_OUT];  // layer-2 GEMM raw output (fp16)
__device__ float  g_dinv[N_NODES];
__device__ __half g_Ah  [(size_t)N_NODES * KP];     // packed A'' = [hi | lo]
__device__ __half g_BhT [(size_t)D_HID * KP];       // packed B''^T n-major: [n][hi|hi]
__device__ int    g_cnt [N_NODES];                  // in-degree (excl self)
__device__ int    g_row [N_NODES + 1];              // CSR row starts
__device__ int    g_fill[N_NODES];                  // fill cursors
__device__ int    g_csrc[N_EDGES];                  // CSR src ids
__device__ float  g_cw  [N_EDGES];                  // CSR edge weights
__device__ int    g_bsum[256];                      // per-block count sums (NB used)
__device__ int    g_bpre[256];                      // exclusive prefix of block sums

// ---------------- degree count / norm ----------------
__global__ void k_cnt_zero() {
    int i = blockIdx.x * blockDim.x + threadIdx.x;
    if (i < N_NODES) g_cnt[i] = 0;
}
__global__ void k_count(const int* __restrict__ ei) {
    int e = blockIdx.x * blockDim.x + threadIdx.x;
    if (e < N_EDGES) atomicAdd(&g_cnt[ei[N_EDGES + e]], 1);
}
__global__ void k_dinv() {
    int i = blockIdx.x * blockDim.x + threadIdx.x;
    if (i < N_NODES) g_dinv[i] = rsqrtf(1.0f + (float)g_cnt[i]);  // +1 self-loop
}

// ---------------- 3-phase scan ----------------
__global__ __launch_bounds__(256)
void k_bsum() {
    __shared__ int sm[256];
    int idx = blockIdx.x * 256 + threadIdx.x;
    sm[threadIdx.x] = (idx < N_NODES) ? g_cnt[idx] : 0;
    __syncthreads();
    for (int off = 128; off > 0; off >>= 1) {
        if (threadIdx.x < off) sm[threadIdx.x] += sm[threadIdx.x + off];
        __syncthreads();
    }
    if (threadIdx.x == 0) g_bsum[blockIdx.x] = sm[0];
}
__global__ __launch_bounds__(256)
void k_scan_bsum() {
    __shared__ int sm[256];
    int t = threadIdx.x;
    sm[t] = (t < NB) ? g_bsum[t] : 0;
    __syncthreads();
    for (int off = 1; off < 256; off <<= 1) {
        int v = (t >= off) ? sm[t - off] : 0;
        __syncthreads();
        sm[t] += v;
        __syncthreads();
    }
    int own = (t < NB) ? g_bsum[t] : 0;
    if (t < NB) g_bpre[t] = sm[t] - own;          // exclusive
    if (t == 255) g_row[N_NODES] = sm[255];       // total
}
__global__ __launch_bounds__(256)
void k_rowfill() {
    __shared__ int sm[256];
    int idx = blockIdx.x * 256 + threadIdx.x;
    int t = threadIdx.x;
    int val = (idx < N_NODES) ? g_cnt[idx] : 0;
    sm[t] = val;
    __syncthreads();
    for (int off = 1; off < 256; off <<= 1) {
        int v = (t >= off) ? sm[t - off] : 0;
        __syncthreads();
        sm[t] += v;
        __syncthreads();
    }
    if (idx < N_NODES) {
        int r = g_bpre[blockIdx.x] + sm[t] - val;  // global exclusive prefix
        g_row[idx]  = r;
        g_fill[idx] = r;
    }
}

__global__ void k_fill(const int* __restrict__ ei) {
    int e = blockIdx.x * blockDim.x + threadIdx.x;
    if (e < N_EDGES) {
        int s = ei[e];
        int d = ei[N_EDGES + e];
        int pos = atomicAdd(&g_fill[d], 1);
        g_csrc[pos] = s;
        g_cw[pos]   = g_dinv[s] * g_dinv[d];
    }
}

// ---------------- packing ----------------
// A'' = [hi | lo] per row; 8 cols per thread, uint4 stores
__global__ void k_pack_x(const float* __restrict__ x) {
    size_t idx = (size_t)blockIdx.x * blockDim.x + threadIdx.x;
    if (idx < (size_t)N_NODES * 64) {
        size_t m = idx >> 6;
        int c8 = (int)(idx & 63) * 8;
        const float* src = x + m * 512 + c8;
        float4 v0 = *(const float4*)src;
        float4 v1 = *(const float4*)(src + 4);
        __half2 hi[4], lo[4];
        float vv[8] = {v0.x, v0.y, v0.z, v0.w, v1.x, v1.y, v1.z, v1.w};
        #pragma unroll
        for (int p = 0; p < 4; p++) {
            __half h0 = __float2half(vv[2 * p]);
            __half h1 = __float2half(vv[2 * p + 1]);
            hi[p] = __halves2half2(h0, h1);
            lo[p] = __halves2half2(__float2half(vv[2 * p]     - __half2float(h0)),
                                   __float2half(vv[2 * p + 1] - __half2float(h1)));
        }
        __half* row = g_Ah + m * KP;
        *(uint4*)(row + c8)       = *(uint4*)hi;
        *(uint4*)(row + 512 + c8) = *(uint4*)lo;
    }
}

// B''^T n-major: both K' halves hold Bhi
template <int N>
__device__ __forceinline__
void packB_body(const float* __restrict__ W) {
    int idx = blockIdx.x * blockDim.x + threadIdx.x;
    if (idx < 512 * N) {
        int k = idx / N, n = idx % N;
        __half hi = __float2half(W[idx]);
        __half* col = g_BhT + (size_t)n * KP;
        col[k]       = hi;
        col[512 + k] = hi;
    }
}
__global__ void k_pack_W1(const float* __restrict__ W) { packB_body<D_HID>(W); }
__global__ void k_pack_W2(const float* __restrict__ W) { packB_body<D_OUT>(W); }

// ---------------- mma.sync m16n8k16 ----------------
__device__ __forceinline__
void mma16816(float* d, const uint32_t* a, const uint32_t* b) {
    asm volatile(
        "mma.sync.aligned.m16n8k16.row.col.f32.f16.f16.f32 "
        "{%0,%1,%2,%3}, {%4,%5,%6,%7}, {%8,%9}, {%0,%1,%2,%3};\n"
        : "+f"(d[0]), "+f"(d[1]), "+f"(d[2]), "+f"(d[3])
        : "r"(a[0]), "r"(a[1]), "r"(a[2]), "r"(a[3]),
          "r"(b[0]), "r"(b[1]));
}

// ---------------- tensor-core GEMM: Ch[M,N] = half(A''[M,KP] @ B''[KP,N]) ----------------
template <int N>
__device__ __forceinline__
void gemm_mma_body(const __half* __restrict__ Ah, const __half* __restrict__ BhT,
                   __half* __restrict__ Ch) {
    constexpr int BM = 128, BK = 32, PITCH = 40;
    __shared__ __half As[2][BM][PITCH];
    __shared__ __half Bs[2][BM][PITCH];

    const int tid  = threadIdx.x;
    const int lane = tid & 31;
    const int wid  = tid >> 5;
    const int warp_m = wid >> 2;
    const int warp_n = wid & 3;
    const int rowBase = blockIdx.y * BM;
    const int colBase = blockIdx.x * BM;

    const int lg  = lane >> 2;
    const int lc2 = (lane & 3) * 2;

    const int r0 = tid >> 2,  s0 = (tid & 3) * 8;
    const int r1 = r0 + 64;
    const uint4 z4 = make_uint4(0, 0, 0, 0);

    float acc[4][4][4];
    #pragma unroll
    for (int i = 0; i < 4; i++)
        #pragma unroll
        for (int j = 0; j < 4; j++)
            #pragma unroll
            for (int q = 0; q < 4; q++) acc[i][j][q] = 0.0f;

    uint4 na0, na1, nb0, nb1;
    {
        int gm0 = rowBase + r0, gm1 = rowBase + r1;
        na0 = (gm0 < N_NODES) ? *(const uint4*)(Ah + (size_t)gm0 * KP + s0) : z4;
        na1 = (gm1 < N_NODES) ? *(const uint4*)(Ah + (size_t)gm1 * KP + s0) : z4;
        nb0 = *(const uint4*)(BhT + (size_t)(colBase + r0) * KP + s0);
        nb1 = *(const uint4*)(BhT + (size_t)(colBase + r1) * KP + s0);
        *(uint4*)&As[0][r0][s0] = na0;
        *(uint4*)&As[0][r1][s0] = na1;
        *(uint4*)&Bs[0][r0][s0] = nb0;
        *(uint4*)&Bs[0][r1][s0] = nb1;
    }
    __syncthreads();

    constexpr int NIT = KP / BK;   // 32
    for (int t = 0; t < NIT; t++) {
        const int buf = t & 1;

        if (t + 1 < NIT) {
            const int k0 = (t + 1) * BK;
            int gm0 = rowBase + r0, gm1 = rowBase + r1;
            na0 = (gm0 < N_NODES) ? *(const uint4*)(Ah + (size_t)gm0 * KP + k0 + s0) : z4;
            na1 = (gm1 < N_NODES) ? *(const uint4*)(Ah + (size_t)gm1 * KP + k0 + s0) : z4;
            nb0 = *(const uint4*)(BhT + (size_t)(colBase + r0) * KP + k0 + s0);
            nb1 = *(const uint4*)(BhT + (size_t)(colBase + r1) * KP + k0 + s0);
        }

        #pragma unroll
        for (int ks = 0; ks < 2; ks++) {
            const int c = ks * 16 + lc2;
            uint32_t afr[4][4], bfr[4][2];
            #pragma unroll
            for (int mf = 0; mf < 4; mf++) {
                int r = warp_m * 64 + mf * 16 + lg;
                afr[mf][0] = *(const uint32_t*)&As[buf][r][c];
                afr[mf][1] = *(const uint32_t*)&As[buf][r + 8][c];
                afr[mf][2] = *(const uint32_t*)&As[buf][r][c + 8];
                afr[mf][3] = *(const uint32_t*)&As[buf][r + 8][c + 8];
            }
            #pragma unroll
            for (int nf = 0; nf < 4; nf++) {
                int n = warp_n * 32 + nf * 8 + lg;
                bfr[nf][0] = *(const uint32_t*)&Bs[buf][n][c];
                bfr[nf][1] = *(const uint32_t*)&Bs[buf][n][c + 8];
            }
            #pragma unroll
            for (int mf = 0; mf < 4; mf++)
                #pragma unroll
                for (int nf = 0; nf < 4; nf++)
                    mma16816(acc[mf][nf], afr[mf], bfr[nf]);
        }

        if (t + 1 < NIT) {
            const int nbuf = buf ^ 1;
            *(uint4*)&As[nbuf][r0][s0] = na0;
            *(uint4*)&As[nbuf][r1][s0] = na1;
            *(uint4*)&Bs[nbuf][r0][s0] = nb0;
            *(uint4*)&Bs[nbuf][r1][s0] = nb1;
        }
        __syncthreads();
    }

    // epilogue: store fp16
    #pragma unroll
    for (int mf = 0; mf < 4; mf++) {
        #pragma unroll
        for (int hh = 0; hh < 2; hh++) {
            int m = rowBase + warp_m * 64 + mf * 16 + lg + hh * 8;
            if (m < N_NODES) {
                #pragma unroll
                for (int nf = 0; nf < 4; nf++) {
                    int n = colBase + warp_n * 32 + nf * 8 + lc2;
                    *(__half2*)(Ch + (size_t)m * N + n) =
                        __floats2half2_rn(acc[mf][nf][hh * 2 + 0], acc[mf][nf][hh * 2 + 1]);
                }
            }
        }
    }
}

__global__ __launch_bounds__(256)
void k_mma_l1() { gemm_mma_body<D_HID>(g_Ah, g_BhT, g_hh); }
__global__ __launch_bounds__(256)
void k_mma_l2() { gemm_mma_body<D_OUT>(g_Ah, g_BhT, g_h2h); }

// ---------------- CSR gather layer 1 ----------------
// dst packed g_Ah row = [hi|lo] of relu( h[i]*ss + b + sum w_j h[src_j] )
__global__ __launch_bounds__(128)
void k_gather_l1(const float* __restrict__ b1) {
    int i = blockIdx.x;
    int col = threadIdx.x * 4;
    float s = g_dinv[i];
    float ss = s * s;

    __half2 hv2[2];
    *(uint2*)hv2 = *(const uint2*)(g_hh + (size_t)i * D_HID + col);
    float2 h0 = __half22float2(hv2[0]);
    float2 h1 = __half22float2(hv2[1]);
    float4 bv = *(const float4*)(b1 + col);
    float4 acc = make_float4(fmaf(h0.x, ss, bv.x), fmaf(h0.y, ss, bv.y),
                             fmaf(h1.x, ss, bv.z), fmaf(h1.y, ss, bv.w));

    int beg = g_row[i], end = g_row[i + 1];
    for (int j = beg; j < end; j++) {
        int   sj = g_csrc[j];
        float w  = g_cw[j];
        __half2 a2[2];
        *(uint2*)a2 = *(const uint2*)(g_hh + (size_t)sj * D_HID + col);
        float2 a0 = __half22float2(a2[0]);
        float2 a1 = __half22float2(a2[1]);
        acc.x = fmaf(a0.x, w, acc.x);
        acc.y = fmaf(a0.y, w, acc.y);
        acc.z = fmaf(a1.x, w, acc.z);
        acc.w = fmaf(a1.y, w, acc.w);
    }
    acc.x = fmaxf(acc.x, 0.f); acc.y = fmaxf(acc.y, 0.f);
    acc.z = fmaxf(acc.z, 0.f); acc.w = fmaxf(acc.w, 0.f);

    // write packed hi|lo directly (replaces pack_agg)
    __half hx = __float2half(acc.x), hy = __float2half(acc.y);
    __half hz = __float2half(acc.z), hw = __float2half(acc.w);
    __half2 hi[2] = { __halves2half2(hx, hy), __halves2half2(hz, hw) };
    __half2 lo[2] = {
        __halves2half2(__float2half(acc.x - __half2float(hx)),
                       __float2half(acc.y - __half2float(hy))),
        __halves2half2(__float2half(acc.z - __half2float(hz)),
                       __float2half(acc.w - __half2float(hw))) };
    __half* row = g_Ah + (size_t)i * KP;
    *(uint2*)(row + col)       = *(uint2*)hi;
    *(uint2*)(row + 512 + col) = *(uint2*)lo;
}

// ---------------- CSR gather layer 2 -> out (fp32) ----------------
__global__ __launch_bounds__(128)
void k_gather_l2(const float* __restrict__ b2, float* __restrict__ out) {
    int i = blockIdx.x;
    int col = threadIdx.x * 2;
    float s = g_dinv[i];
    float ss = s * s;

    float2 hv = __half22float2(*(const __half2*)(g_h2h + (size_t)i * D_OUT + col));
    float2 bv = *(const float2*)(b2 + col);
    float2 acc = make_float2(fmaf(hv.x, ss, bv.x), fmaf(hv.y, ss, bv.y));

    int beg = g_row[i], end = g_row[i + 1];
    for (int j = beg; j < end; j++) {
        int   sj = g_csrc[j];
        float w  = g_cw[j];
        float2 a = __half22float2(*(const __half2*)(g_h2h + (size_t)sj * D_OUT + col));
        acc.x = fmaf(a.x, w, acc.x);
        acc.y = fmaf(a.y, w, acc.y);
    }
    *(float2*)(out + (size_t)i * D_OUT + col) = acc;
}

// ---------------- launch ----------------
extern "C" void kernel_launch(void* const* d_in, const int* in_sizes, int n_in,
                              void* d_out, int out_size) {
    const float* x  = (const float*)d_in[0];
    const int*   ei = (const int*)d_in[1];     // int32 (JAX x64 disabled)
    const float* W1 = (const float*)d_in[2];
    const float* b1 = (const float*)d_in[3];
    const float* W2 = (const float*)d_in[4];
    const float* b2 = (const float*)d_in[5];
    float* out = (float*)d_out;

    // 1) degrees, dinv, parallel scan, CSR fill
    k_cnt_zero<<<(N_NODES + 255) / 256, 256>>>();
    k_count<<<(N_EDGES + 255) / 256, 256>>>(ei);
    k_dinv<<<(N_NODES + 255) / 256, 256>>>();
    k_bsum<<<NB, 256>>>();
    k_scan_bsum<<<1, 256>>>();
    k_rowfill<<<NB, 256>>>();
    k_fill<<<(N_EDGES + 255) / 256, 256>>>(ei);

    // 2) layer 1: pack, tensor GEMM (fp16 out), CSR gather (writes packed A'')
    {
        size_t tot = (size_t)N_NODES * 64;
        k_pack_x<<<(int)((tot + 255) / 256), 256>>>(x);
        k_pack_W1<<<(512 * D_HID + 255) / 256, 256>>>(W1);
        dim3 grid(D_HID / 128, (N_NODES + 127) / 128);
        k_mma_l1<<<grid, 256>>>();
        k_gather_l1<<<N_NODES, 128>>>(b1);
    }
    // 3) layer 2: pack W2, tensor GEMM (fp16 out), CSR gather -> d_out
    {
        k_pack_W2<<<(512 * D_OUT + 255) / 256, 256>>>(W2);
        dim3 grid(D_OUT / 128, (N_NODES + 127) / 128);
        k_mma_l2<<<grid, 256>>>();
        k_gather_l2<<<N_NODES, 128>>>(b2, out);
    }
}

// round 11
// speedup vs baseline: 7.1529x; 1.5324x over previous
#include <cuda_runtime.h>
#include <cuda_fp16.h>
#include <cstdint>

#define N_NODES 50000
#define N_EDGES 400000
#define D_IN    512
#define D_HID   512
#define D_OUT   256
#define KP      512    // plain fp16 GEMM, no split
#define NB      196    // scan blocks: 196*256 >= 50000

// ---------------- scratch (device globals; referenced ONLY from device code) ----------------
__device__ __half g_hh  [(size_t)N_NODES * D_HID];  // layer-1 GEMM output (fp16)
__device__ __half g_h2h [(size_t)N_NODES * D_OUT];  // layer-2 GEMM output (fp16)
__device__ float  g_dinv[N_NODES];
__device__ __half g_Ah  [(size_t)N_NODES * KP];     // fp16 A
__device__ __half g_BhT [(size_t)D_HID * KP];       // fp16 B^T, n-major: [n][k]
__device__ int    g_cnt [N_NODES];
__device__ int    g_row [N_NODES + 1];
__device__ int    g_fill[N_NODES];
__device__ int    g_csrc[N_EDGES];
__device__ float  g_cw  [N_EDGES];
__device__ int    g_bsum[256];
__device__ int    g_bpre[256];

// ---------------- degree count / norm ----------------
__global__ void k_cnt_zero() {
    int i = blockIdx.x * blockDim.x + threadIdx.x;
    if (i < N_NODES) g_cnt[i] = 0;
}
__global__ void k_count(const int* __restrict__ ei) {
    int e = blockIdx.x * blockDim.x + threadIdx.x;
    if (e < N_EDGES) atomicAdd(&g_cnt[ei[N_EDGES + e]], 1);
}
__global__ void k_dinv() {
    int i = blockIdx.x * blockDim.x + threadIdx.x;
    if (i < N_NODES) g_dinv[i] = rsqrtf(1.0f + (float)g_cnt[i]);
}

// ---------------- 3-phase scan ----------------
__global__ __launch_bounds__(256)
void k_bsum() {
    __shared__ int sm[256];
    int idx = blockIdx.x * 256 + threadIdx.x;
    sm[threadIdx.x] = (idx < N_NODES) ? g_cnt[idx] : 0;
    __syncthreads();
    for (int off = 128; off > 0; off >>= 1) {
        if (threadIdx.x < off) sm[threadIdx.x] += sm[threadIdx.x + off];
        __syncthreads();
    }
    if (threadIdx.x == 0) g_bsum[blockIdx.x] = sm[0];
}
__global__ __launch_bounds__(256)
void k_scan_bsum() {
    __shared__ int sm[256];
    int t = threadIdx.x;
    sm[t] = (t < NB) ? g_bsum[t] : 0;
    __syncthreads();
    for (int off = 1; off < 256; off <<= 1) {
        int v = (t >= off) ? sm[t - off] : 0;
        __syncthreads();
        sm[t] += v;
        __syncthreads();
    }
    int own = (t < NB) ? g_bsum[t] : 0;
    if (t < NB) g_bpre[t] = sm[t] - own;
    if (t == 255) g_row[N_NODES] = sm[255];
}
__global__ __launch_bounds__(256)
void k_rowfill() {
    __shared__ int sm[256];
    int idx = blockIdx.x * 256 + threadIdx.x;
    int t = threadIdx.x;
    int val = (idx < N_NODES) ? g_cnt[idx] : 0;
    sm[t] = val;
    __syncthreads();
    for (int off = 1; off < 256; off <<= 1) {
        int v = (t >= off) ? sm[t - off] : 0;
        __syncthreads();
        sm[t] += v;
        __syncthreads();
    }
    if (idx < N_NODES) {
        int r = g_bpre[blockIdx.x] + sm[t] - val;
        g_row[idx]  = r;
        g_fill[idx] = r;
    }
}
__global__ void k_fill(const int* __restrict__ ei) {
    int e = blockIdx.x * blockDim.x + threadIdx.x;
    if (e < N_EDGES) {
        int s = ei[e];
        int d = ei[N_EDGES + e];
        int pos = atomicAdd(&g_fill[d], 1);
        g_csrc[pos] = s;
        g_cw[pos]   = g_dinv[s] * g_dinv[d];
    }
}

// ---------------- packing ----------------
// fp32 -> fp16, 8 cols per thread, uint4 store
__global__ void k_pack_x(const float* __restrict__ x) {
    size_t idx = (size_t)blockIdx.x * blockDim.x + threadIdx.x;
    if (idx < (size_t)N_NODES * 64) {
        size_t m = idx >> 6;
        int c8 = (int)(idx & 63) * 8;
        const float* src = x + m * 512 + c8;
        float4 v0 = *(const float4*)src;
        float4 v1 = *(const float4*)(src + 4);
        __half2 h[4] = {
            __floats2half2_rn(v0.x, v0.y), __floats2half2_rn(v0.z, v0.w),
            __floats2half2_rn(v1.x, v1.y), __floats2half2_rn(v1.z, v1.w) };
        *(uint4*)(g_Ah + m * KP + c8) = *(uint4*)h;
    }
}
// B^T n-major
template <int N>
__device__ __forceinline__
void packB_body(const float* __restrict__ W) {
    int idx = blockIdx.x * blockDim.x + threadIdx.x;
    if (idx < 512 * N) {
        int k = idx / N, n = idx % N;
        g_BhT[(size_t)n * KP + k] = __float2half(W[idx]);
    }
}
__global__ void k_pack_W1(const float* __restrict__ W) { packB_body<D_HID>(W); }
__global__ void k_pack_W2(const float* __restrict__ W) { packB_body<D_OUT>(W); }

// ---------------- mma.sync m16n8k16 ----------------
__device__ __forceinline__
void mma16816(float* d, const uint32_t* a, const uint32_t* b) {
    asm volatile(
        "mma.sync.aligned.m16n8k16.row.col.f32.f16.f16.f32 "
        "{%0,%1,%2,%3}, {%4,%5,%6,%7}, {%8,%9}, {%0,%1,%2,%3};\n"
        : "+f"(d[0]), "+f"(d[1]), "+f"(d[2]), "+f"(d[3])
        : "r"(a[0]), "r"(a[1]), "r"(a[2]), "r"(a[3]),
          "r"(b[0]), "r"(b[1]));
}

// ---------------- tensor-core GEMM: Ch[M,N] = half(A[M,512] @ B[512,N]) ----------------
template <int N>
__device__ __forceinline__
void gemm_mma_body(const __half* __restrict__ Ah, const __half* __restrict__ BhT,
                   __half* __restrict__ Ch) {
    constexpr int BM = 128, BK = 32, PITCH = 40;
    __shared__ __half As[2][BM][PITCH];
    __shared__ __half Bs[2][BM][PITCH];

    const int tid  = threadIdx.x;
    const int lane = tid & 31;
    const int wid  = tid >> 5;
    const int warp_m = wid >> 2;
    const int warp_n = wid & 3;
    const int rowBase = blockIdx.y * BM;
    const int colBase = blockIdx.x * BM;

    const int lg  = lane >> 2;
    const int lc2 = (lane & 3) * 2;

    const int r0 = tid >> 2,  s0 = (tid & 3) * 8;
    const int r1 = r0 + 64;
    const uint4 z4 = make_uint4(0, 0, 0, 0);

    float acc[4][4][4];
    #pragma unroll
    for (int i = 0; i < 4; i++)
        #pragma unroll
        for (int j = 0; j < 4; j++)
            #pragma unroll
            for (int q = 0; q < 4; q++) acc[i][j][q] = 0.0f;

    uint4 na0, na1, nb0, nb1;
    {
        int gm0 = rowBase + r0, gm1 = rowBase + r1;
        na0 = (gm0 < N_NODES) ? *(const uint4*)(Ah + (size_t)gm0 * KP + s0) : z4;
        na1 = (gm1 < N_NODES) ? *(const uint4*)(Ah + (size_t)gm1 * KP + s0) : z4;
        nb0 = *(const uint4*)(BhT + (size_t)(colBase + r0) * KP + s0);
        nb1 = *(const uint4*)(BhT + (size_t)(colBase + r1) * KP + s0);
        *(uint4*)&As[0][r0][s0] = na0;
        *(uint4*)&As[0][r1][s0] = na1;
        *(uint4*)&Bs[0][r0][s0] = nb0;
        *(uint4*)&Bs[0][r1][s0] = nb1;
    }
    __syncthreads();

    constexpr int NIT = KP / BK;   // 16
    for (int t = 0; t < NIT; t++) {
        const int buf = t & 1;

        if (t + 1 < NIT) {
            const int k0 = (t + 1) * BK;
            int gm0 = rowBase + r0, gm1 = rowBase + r1;
            na0 = (gm0 < N_NODES) ? *(const uint4*)(Ah + (size_t)gm0 * KP + k0 + s0) : z4;
            na1 = (gm1 < N_NODES) ? *(const uint4*)(Ah + (size_t)gm1 * KP + k0 + s0) : z4;
            nb0 = *(const uint4*)(BhT + (size_t)(colBase + r0) * KP + k0 + s0);
            nb1 = *(const uint4*)(BhT + (size_t)(colBase + r1) * KP + k0 + s0);
        }

        #pragma unroll
        for (int ks = 0; ks < 2; ks++) {
            const int c = ks * 16 + lc2;
            uint32_t afr[4][4], bfr[4][2];
            #pragma unroll
            for (int mf = 0; mf < 4; mf++) {
                int r = warp_m * 64 + mf * 16 + lg;
                afr[mf][0] = *(const uint32_t*)&As[buf][r][c];
                afr[mf][1] = *(const uint32_t*)&As[buf][r + 8][c];
                afr[mf][2] = *(const uint32_t*)&As[buf][r][c + 8];
                afr[mf][3] = *(const uint32_t*)&As[buf][r + 8][c + 8];
            }
            #pragma unroll
            for (int nf = 0; nf < 4; nf++) {
                int n = warp_n * 32 + nf * 8 + lg;
                bfr[nf][0] = *(const uint32_t*)&Bs[buf][n][c];
                bfr[nf][1] = *(const uint32_t*)&Bs[buf][n][c + 8];
            }
            #pragma unroll
            for (int mf = 0; mf < 4; mf++)
                #pragma unroll
                for (int nf = 0; nf < 4; nf++)
                    mma16816(acc[mf][nf], afr[mf], bfr[nf]);
        }

        if (t + 1 < NIT) {
            const int nbuf = buf ^ 1;
            *(uint4*)&As[nbuf][r0][s0] = na0;
            *(uint4*)&As[nbuf][r1][s0] = na1;
            *(uint4*)&Bs[nbuf][r0][s0] = nb0;
            *(uint4*)&Bs[nbuf][r1][s0] = nb1;
        }
        __syncthreads();
    }

    #pragma unroll
    for (int mf = 0; mf < 4; mf++) {
        #pragma unroll
        for (int hh = 0; hh < 2; hh++) {
            int m = rowBase + warp_m * 64 + mf * 16 + lg + hh * 8;
            if (m < N_NODES) {
                #pragma unroll
                for (int nf = 0; nf < 4; nf++) {
                    int n = colBase + warp_n * 32 + nf * 8 + lc2;
                    *(__half2*)(Ch + (size_t)m * N + n) =
                        __floats2half2_rn(acc[mf][nf][hh * 2 + 0], acc[mf][nf][hh * 2 + 1]);
                }
            }
        }
    }
}

__global__ __launch_bounds__(256)
void k_mma_l1() { gemm_mma_body<D_HID>(g_Ah, g_BhT, g_hh); }
__global__ __launch_bounds__(256)
void k_mma_l2() { gemm_mma_body<D_OUT>(g_Ah, g_BhT, g_h2h); }

// ---------------- CSR gather layer 1: writes fp16 A for layer 2 ----------------
__global__ __launch_bounds__(128)
void k_gather_l1(const float* __restrict__ b1) {
    int i = blockIdx.x;
    int col = threadIdx.x * 4;
    float s = g_dinv[i];
    float ss = s * s;

    __half2 hv2[2];
    *(uint2*)hv2 = *(const uint2*)(g_hh + (size_t)i * D_HID + col);
    float2 h0 = __half22float2(hv2[0]);
    float2 h1 = __half22float2(hv2[1]);
    float4 bv = *(const float4*)(b1 + col);
    float4 acc = make_float4(fmaf(h0.x, ss, bv.x), fmaf(h0.y, ss, bv.y),
                             fmaf(h1.x, ss, bv.z), fmaf(h1.y, ss, bv.w));

    int beg = g_row[i], end = g_row[i + 1];
    for (int j = beg; j < end; j++) {
        int   sj = g_csrc[j];
        float w  = g_cw[j];
        __half2 a2[2];
        *(uint2*)a2 = *(const uint2*)(g_hh + (size_t)sj * D_HID + col);
        float2 a0 = __half22float2(a2[0]);
        float2 a1 = __half22float2(a2[1]);
        acc.x = fmaf(a0.x, w, acc.x);
        acc.y = fmaf(a0.y, w, acc.y);
        acc.z = fmaf(a1.x, w, acc.z);
        acc.w = fmaf(a1.y, w, acc.w);
    }
    acc.x = fmaxf(acc.x, 0.f); acc.y = fmaxf(acc.y, 0.f);
    acc.z = fmaxf(acc.z, 0.f); acc.w = fmaxf(acc.w, 0.f);

    __half2 h[2] = { __floats2half2_rn(acc.x, acc.y),
                     __floats2half2_rn(acc.z, acc.w) };
    *(uint2*)(g_Ah + (size_t)i * KP + col) = *(uint2*)h;
}

// ---------------- CSR gather layer 2 -> out (fp32) ----------------
__global__ __launch_bounds__(128)
void k_gather_l2(const float* __restrict__ b2, float* __restrict__ out) {
    int i = blockIdx.x;
    int col = threadIdx.x * 2;
    float s = g_dinv[i];
    float ss = s * s;

    float2 hv = __half22float2(*(const __half2*)(g_h2h + (size_t)i * D_OUT + col));
    float2 bv = *(const float2*)(b2 + col);
    float2 acc = make_float2(fmaf(hv.x, ss, bv.x), fmaf(hv.y, ss, bv.y));

    int beg = g_row[i], end = g_row[i + 1];
    for (int j = beg; j < end; j++) {
        int   sj = g_csrc[j];
        float w  = g_cw[j];
        float2 a = __half22float2(*(const __half2*)(g_h2h + (size_t)sj * D_OUT + col));
        acc.x = fmaf(a.x, w, acc.x);
        acc.y = fmaf(a.y, w, acc.y);
    }
    *(float2*)(out + (size_t)i * D_OUT + col) = acc;
}

// ---------------- launch ----------------
extern "C" void kernel_launch(void* const* d_in, const int* in_sizes, int n_in,
                              void* d_out, int out_size) {
    const float* x  = (const float*)d_in[0];
    const int*   ei = (const int*)d_in[1];     // int32 (JAX x64 disabled)
    const float* W1 = (const float*)d_in[2];
    const float* b1 = (const float*)d_in[3];
    const float* W2 = (const float*)d_in[4];
    const float* b2 = (const float*)d_in[5];
    float* out = (float*)d_out;

    // 1) degrees, dinv, parallel scan, CSR fill
    k_cnt_zero<<<(N_NODES + 255) / 256, 256>>>();
    k_count<<<(N_EDGES + 255) / 256, 256>>>(ei);
    k_dinv<<<(N_NODES + 255) / 256, 256>>>();
    k_bsum<<<NB, 256>>>();
    k_scan_bsum<<<1, 256>>>();
    k_rowfill<<<NB, 256>>>();
    k_fill<<<(N_EDGES + 255) / 256, 256>>>(ei);

    // 2) layer 1: pack, fp16 tensor GEMM, CSR gather (writes fp16 A for layer 2)
    {
        size_t tot = (size_t)N_NODES * 64;
        k_pack_x<<<(int)((tot + 255) / 256), 256>>>(x);
        k_pack_W1<<<(512 * D_HID + 255) / 256, 256>>>(W1);
        dim3 grid(D_HID / 128, (N_NODES + 127) / 128);
        k_mma_l1<<<grid, 256>>>();
        k_gather_l1<<<N_NODES, 128>>>(b1);
    }
    // 3) layer 2: pack W2, fp16 tensor GEMM, CSR gather -> d_out
    {
        k_pack_W2<<<(512 * D_OUT + 255) / 256, 256>>>(W2);
        dim3 grid(D_OUT / 128, (N_NODES + 127) / 128);
        k_mma_l2<<<grid, 256>>>();
        k_gather_l2<<<N_NODES, 128>>>(b2, out);
    }
}

// round 12
// speedup vs baseline: 7.1576x; 1.0007x over previous
#include <cuda_runtime.h>
#include <cuda_fp16.h>
#include <cstdint>

#define N_NODES 50000
#define N_EDGES 400000
#define D_IN    512
#define D_HID   512
#define D_OUT   256
#define KP      512    // plain fp16 GEMM
#define NB      196    // scan blocks: 196*256 >= 50000

// ---------------- scratch (device globals; referenced ONLY from device code) ----------------
__device__ __half g_hh  [(size_t)N_NODES * D_HID];  // layer-1 GEMM output (fp16)
__device__ __half g_h2h [(size_t)N_NODES * D_OUT];  // layer-2 GEMM output (fp16)
__device__ float  g_dinv[N_NODES];
__device__ __half g_Ah  [(size_t)N_NODES * KP];     // fp16 A
__device__ __half g_BhT [(size_t)D_HID * KP];       // fp16 B^T, n-major
__device__ int    g_cnt [N_NODES];
__device__ int    g_row [N_NODES + 1];
__device__ int    g_fill[N_NODES];
__device__ int    g_csrc[N_EDGES];
__device__ float  g_cw  [N_EDGES];
__device__ int    g_bsum[256];
__device__ int    g_bpre[256];

// ---------------- degree count ----------------
__global__ void k_cnt_zero() {
    int i = blockIdx.x * blockDim.x + threadIdx.x;
    if (i < N_NODES) g_cnt[i] = 0;
}
__global__ void k_count(const int* __restrict__ ei) {
    int e = blockIdx.x * blockDim.x + threadIdx.x;
    if (e < N_EDGES) atomicAdd(&g_cnt[ei[N_EDGES + e]], 1);
}

// ---------------- fused dinv + per-block count sum ----------------
__global__ __launch_bounds__(256)
void k_dinv_bsum() {
    __shared__ int sm[256];
    int idx = blockIdx.x * 256 + threadIdx.x;
    int c = 0;
    if (idx < N_NODES) {
        c = g_cnt[idx];
        g_dinv[idx] = rsqrtf(1.0f + (float)c);
    }
    sm[threadIdx.x] = c;
    __syncthreads();
    for (int off = 128; off > 0; off >>= 1) {
        if (threadIdx.x < off) sm[threadIdx.x] += sm[threadIdx.x + off];
        __syncthreads();
    }
    if (threadIdx.x == 0) g_bsum[blockIdx.x] = sm[0];
}

__global__ __launch_bounds__(256)
void k_scan_bsum() {
    __shared__ int sm[256];
    int t = threadIdx.x;
    sm[t] = (t < NB) ? g_bsum[t] : 0;
    __syncthreads();
    for (int off = 1; off < 256; off <<= 1) {
        int v = (t >= off) ? sm[t - off] : 0;
        __syncthreads();
        sm[t] += v;
        __syncthreads();
    }
    int own = (t < NB) ? g_bsum[t] : 0;
    if (t < NB) g_bpre[t] = sm[t] - own;
    if (t == 255) g_row[N_NODES] = sm[255];
}
__global__ __launch_bounds__(256)
void k_rowfill() {
    __shared__ int sm[256];
    int idx = blockIdx.x * 256 + threadIdx.x;
    int t = threadIdx.x;
    int val = (idx < N_NODES) ? g_cnt[idx] : 0;
    sm[t] = val;
    __syncthreads();
    for (int off = 1; off < 256; off <<= 1) {
        int v = (t >= off) ? sm[t - off] : 0;
        __syncthreads();
        sm[t] += v;
        __syncthreads();
    }
    if (idx < N_NODES) {
        int r = g_bpre[blockIdx.x] + sm[t] - val;
        g_row[idx]  = r;
        g_fill[idx] = r;
    }
}
__global__ void k_fill(const int* __restrict__ ei) {
    int e = blockIdx.x * blockDim.x + threadIdx.x;
    if (e < N_EDGES) {
        int s = ei[e];
        int d = ei[N_EDGES + e];
        int pos = atomicAdd(&g_fill[d], 1);
        g_csrc[pos] = s;
        g_cw[pos]   = g_dinv[s] * g_dinv[d];
    }
}

// ---------------- packing ----------------
__global__ void k_pack_x(const float* __restrict__ x) {
    size_t idx = (size_t)blockIdx.x * blockDim.x + threadIdx.x;
    if (idx < (size_t)N_NODES * 64) {
        size_t m = idx >> 6;
        int c8 = (int)(idx & 63) * 8;
        const float* src = x + m * 512 + c8;
        float4 v0 = *(const float4*)src;
        float4 v1 = *(const float4*)(src + 4);
        __half2 h[4] = {
            __floats2half2_rn(v0.x, v0.y), __floats2half2_rn(v0.z, v0.w),
            __floats2half2_rn(v1.x, v1.y), __floats2half2_rn(v1.z, v1.w) };
        *(uint4*)(g_Ah + m * KP + c8) = *(uint4*)h;
    }
}
template <int N>
__device__ __forceinline__
void packB_body(const float* __restrict__ W) {
    int idx = blockIdx.x * blockDim.x + threadIdx.x;
    if (idx < 512 * N) {
        int k = idx / N, n = idx % N;
        g_BhT[(size_t)n * KP + k] = __float2half(W[idx]);
    }
}
__global__ void k_pack_W1(const float* __restrict__ W) { packB_body<D_HID>(W); }
__global__ void k_pack_W2(const float* __restrict__ W) { packB_body<D_OUT>(W); }

// ---------------- mma.sync m16n8k16 ----------------
__device__ __forceinline__
void mma16816(float* d, const uint32_t* a, const uint32_t* b) {
    asm volatile(
        "mma.sync.aligned.m16n8k16.row.col.f32.f16.f16.f32 "
        "{%0,%1,%2,%3}, {%4,%5,%6,%7}, {%8,%9}, {%0,%1,%2,%3};\n"
        : "+f"(d[0]), "+f"(d[1]), "+f"(d[2]), "+f"(d[3])
        : "r"(a[0]), "r"(a[1]), "r"(a[2]), "r"(a[3]),
          "r"(b[0]), "r"(b[1]));
}

// ---------------- tensor-core GEMM: Ch[M,N] = half(A[M,512] @ B[512,N]) ----------------
template <int N>
__device__ __forceinline__
void gemm_mma_body(const __half* __restrict__ Ah, const __half* __restrict__ BhT,
                   __half* __restrict__ Ch) {
    constexpr int BM = 128, BK = 32, PITCH = 40;
    __shared__ __half As[2][BM][PITCH];
    __shared__ __half Bs[2][BM][PITCH];

    const int tid  = threadIdx.x;
    const int lane = tid & 31;
    const int wid  = tid >> 5;
    const int warp_m = wid >> 2;
    const int warp_n = wid & 3;
    const int rowBase = blockIdx.y * BM;
    const int colBase = blockIdx.x * BM;

    const int lg  = lane >> 2;
    const int lc2 = (lane & 3) * 2;

    const int r0 = tid >> 2,  s0 = (tid & 3) * 8;
    const int r1 = r0 + 64;
    const uint4 z4 = make_uint4(0, 0, 0, 0);

    float acc[4][4][4];
    #pragma unroll
    for (int i = 0; i < 4; i++)
        #pragma unroll
        for (int j = 0; j < 4; j++)
            #pragma unroll
            for (int q = 0; q < 4; q++) acc[i][j][q] = 0.0f;

    uint4 na0, na1, nb0, nb1;
    {
        int gm0 = rowBase + r0, gm1 = rowBase + r1;
        na0 = (gm0 < N_NODES) ? *(const uint4*)(Ah + (size_t)gm0 * KP + s0) : z4;
        na1 = (gm1 < N_NODES) ? *(const uint4*)(Ah + (size_t)gm1 * KP + s0) : z4;
        nb0 = *(const uint4*)(BhT + (size_t)(colBase + r0) * KP + s0);
        nb1 = *(const uint4*)(BhT + (size_t)(colBase + r1) * KP + s0);
        *(uint4*)&As[0][r0][s0] = na0;
        *(uint4*)&As[0][r1][s0] = na1;
        *(uint4*)&Bs[0][r0][s0] = nb0;
        *(uint4*)&Bs[0][r1][s0] = nb1;
    }
    __syncthreads();

    constexpr int NIT = KP / BK;   // 16
    for (int t = 0; t < NIT; t++) {
        const int buf = t & 1;

        if (t + 1 < NIT) {
            const int k0 = (t + 1) * BK;
            int gm0 = rowBase + r0, gm1 = rowBase + r1;
            na0 = (gm0 < N_NODES) ? *(const uint4*)(Ah + (size_t)gm0 * KP + k0 + s0) : z4;
            na1 = (gm1 < N_NODES) ? *(const uint4*)(Ah + (size_t)gm1 * KP + k0 + s0) : z4;
            nb0 = *(const uint4*)(BhT + (size_t)(colBase + r0) * KP + k0 + s0);
            nb1 = *(const uint4*)(BhT + (size_t)(colBase + r1) * KP + k0 + s0);
        }

        #pragma unroll
        for (int ks = 0; ks < 2; ks++) {
            const int c = ks * 16 + lc2;
            uint32_t afr[4][4], bfr[4][2];
            #pragma unroll
            for (int mf = 0; mf < 4; mf++) {
                int r = warp_m * 64 + mf * 16 + lg;
                afr[mf][0] = *(const uint32_t*)&As[buf][r][c];
                afr[mf][1] = *(const uint32_t*)&As[buf][r + 8][c];
                afr[mf][2] = *(const uint32_t*)&As[buf][r][c + 8];
                afr[mf][3] = *(const uint32_t*)&As[buf][r + 8][c + 8];
            }
            #pragma unroll
            for (int nf = 0; nf < 4; nf++) {
                int n = warp_n * 32 + nf * 8 + lg;
                bfr[nf][0] = *(const uint32_t*)&Bs[buf][n][c];
                bfr[nf][1] = *(const uint32_t*)&Bs[buf][n][c + 8];
            }
            #pragma unroll
            for (int mf = 0; mf < 4; mf++)
                #pragma unroll
                for (int nf = 0; nf < 4; nf++)
                    mma16816(acc[mf][nf], afr[mf], bfr[nf]);
        }

        if (t + 1 < NIT) {
            const int nbuf = buf ^ 1;
            *(uint4*)&As[nbuf][r0][s0] = na0;
            *(uint4*)&As[nbuf][r1][s0] = na1;
            *(uint4*)&Bs[nbuf][r0][s0] = nb0;
            *(uint4*)&Bs[nbuf][r1][s0] = nb1;
        }
        __syncthreads();
    }

    #pragma unroll
    for (int mf = 0; mf < 4; mf++) {
        #pragma unroll
        for (int hh = 0; hh < 2; hh++) {
            int m = rowBase + warp_m * 64 + mf * 16 + lg + hh * 8;
            if (m < N_NODES) {
                #pragma unroll
                for (int nf = 0; nf < 4; nf++) {
                    int n = colBase + warp_n * 32 + nf * 8 + lc2;
                    *(__half2*)(Ch + (size_t)m * N + n) =
                        __floats2half2_rn(acc[mf][nf][hh * 2 + 0], acc[mf][nf][hh * 2 + 1]);
                }
            }
        }
    }
}

__global__ __launch_bounds__(256)
void k_mma_l1() { gemm_mma_body<D_HID>(g_Ah, g_BhT, g_hh); }
__global__ __launch_bounds__(256)
void k_mma_l2() { gemm_mma_body<D_OUT>(g_Ah, g_BhT, g_h2h); }

// ---------------- CSR gather layer 1 (4-wide edge unroll): writes fp16 A ----------------
__global__ __launch_bounds__(128)
void k_gather_l1(const float* __restrict__ b1) {
    int i = blockIdx.x;
    int col = threadIdx.x * 4;
    float s = g_dinv[i];
    float ss = s * s;

    __half2 hv2[2];
    *(uint2*)hv2 = *(const uint2*)(g_hh + (size_t)i * D_HID + col);
    float2 h0 = __half22float2(hv2[0]);
    float2 h1 = __half22float2(hv2[1]);
    float4 bv = *(const float4*)(b1 + col);
    float4 acc = make_float4(fmaf(h0.x, ss, bv.x), fmaf(h0.y, ss, bv.y),
                             fmaf(h1.x, ss, bv.z), fmaf(h1.y, ss, bv.w));

    int beg = g_row[i], end = g_row[i + 1];
    int j = beg;
    for (; j + 3 < end; j += 4) {
        int   s0 = g_csrc[j],     s1 = g_csrc[j + 1];
        int   s2 = g_csrc[j + 2], s3 = g_csrc[j + 3];
        float w0 = g_cw[j],       w1 = g_cw[j + 1];
        float w2 = g_cw[j + 2],   w3 = g_cw[j + 3];
        uint2 r0 = *(const uint2*)(g_hh + (size_t)s0 * D_HID + col);
        uint2 r1 = *(const uint2*)(g_hh + (size_t)s1 * D_HID + col);
        uint2 r2 = *(const uint2*)(g_hh + (size_t)s2 * D_HID + col);
        uint2 r3 = *(const uint2*)(g_hh + (size_t)s3 * D_HID + col);
        const __half2* p0 = (const __half2*)&r0;
        const __half2* p1 = (const __half2*)&r1;
        const __half2* p2 = (const __half2*)&r2;
        const __half2* p3 = (const __half2*)&r3;
        float2 a;
        a = __half22float2(p0[0]); acc.x = fmaf(a.x, w0, acc.x); acc.y = fmaf(a.y, w0, acc.y);
        a = __half22float2(p0[1]); acc.z = fmaf(a.x, w0, acc.z); acc.w = fmaf(a.y, w0, acc.w);
        a = __half22float2(p1[0]); acc.x = fmaf(a.x, w1, acc.x); acc.y = fmaf(a.y, w1, acc.y);
        a = __half22float2(p1[1]); acc.z = fmaf(a.x, w1, acc.z); acc.w = fmaf(a.y, w1, acc.w);
        a = __half22float2(p2[0]); acc.x = fmaf(a.x, w2, acc.x); acc.y = fmaf(a.y, w2, acc.y);
        a = __half22float2(p2[1]); acc.z = fmaf(a.x, w2, acc.z); acc.w = fmaf(a.y, w2, acc.w);
        a = __half22float2(p3[0]); acc.x = fmaf(a.x, w3, acc.x); acc.y = fmaf(a.y, w3, acc.y);
        a = __half22float2(p3[1]); acc.z = fmaf(a.x, w3, acc.z); acc.w = fmaf(a.y, w3, acc.w);
    }
    for (; j < end; j++) {
        int   sj = g_csrc[j];
        float w  = g_cw[j];
        uint2 r = *(const uint2*)(g_hh + (size_t)sj * D_HID + col);
        const __half2* p = (const __half2*)&r;
        float2 a0 = __half22float2(p[0]);
        float2 a1 = __half22float2(p[1]);
        acc.x = fmaf(a0.x, w, acc.x);
        acc.y = fmaf(a0.y, w, acc.y);
        acc.z = fmaf(a1.x, w, acc.z);
        acc.w = fmaf(a1.y, w, acc.w);
    }
    acc.x = fmaxf(acc.x, 0.f); acc.y = fmaxf(acc.y, 0.f);
    acc.z = fmaxf(acc.z, 0.f); acc.w = fmaxf(acc.w, 0.f);

    __half2 h[2] = { __floats2half2_rn(acc.x, acc.y),
                     __floats2half2_rn(acc.z, acc.w) };
    *(uint2*)(g_Ah + (size_t)i * KP + col) = *(uint2*)h;
}

// ---------------- CSR gather layer 2 (4-wide edge unroll) -> out (fp32) ----------------
__global__ __launch_bounds__(128)
void k_gather_l2(const float* __restrict__ b2, float* __restrict__ out) {
    int i = blockIdx.x;
    int col = threadIdx.x * 2;
    float s = g_dinv[i];
    float ss = s * s;

    float2 hv = __half22float2(*(const __half2*)(g_h2h + (size_t)i * D_OUT + col));
    float2 bv = *(const float2*)(b2 + col);
    float2 acc = make_float2(fmaf(hv.x, ss, bv.x), fmaf(hv.y, ss, bv.y));

    int beg = g_row[i], end = g_row[i + 1];
    int j = beg;
    for (; j + 3 < end; j += 4) {
        int   s0 = g_csrc[j],     s1 = g_csrc[j + 1];
        int   s2 = g_csrc[j + 2], s3 = g_csrc[j + 3];
        float w0 = g_cw[j],       w1 = g_cw[j + 1];
        float w2 = g_cw[j + 2],   w3 = g_cw[j + 3];
        __half2 q0 = *(const __half2*)(g_h2h + (size_t)s0 * D_OUT + col);
        __half2 q1 = *(const __half2*)(g_h2h + (size_t)s1 * D_OUT + col);
        __half2 q2 = *(const __half2*)(g_h2h + (size_t)s2 * D_OUT + col);
        __half2 q3 = *(const __half2*)(g_h2h + (size_t)s3 * D_OUT + col);
        float2 a;
        a = __half22float2(q0); acc.x = fmaf(a.x, w0, acc.x); acc.y = fmaf(a.y, w0, acc.y);
        a = __half22float2(q1); acc.x = fmaf(a.x, w1, acc.x); acc.y = fmaf(a.y, w1, acc.y);
        a = __half22float2(q2); acc.x = fmaf(a.x, w2, acc.x); acc.y = fmaf(a.y, w2, acc.y);
        a = __half22float2(q3); acc.x = fmaf(a.x, w3, acc.x); acc.y = fmaf(a.y, w3, acc.y);
    }
    for (; j < end; j++) {
        int   sj = g_csrc[j];
        float w  = g_cw[j];
        float2 a = __half22float2(*(const __half2*)(g_h2h + (size_t)sj * D_OUT + col));
        acc.x = fmaf(a.x, w, acc.x);
        acc.y = fmaf(a.y, w, acc.y);
    }
    *(float2*)(out + (size_t)i * D_OUT + col) = acc;
}

// ---------------- launch ----------------
extern "C" void kernel_launch(void* const* d_in, const int* in_sizes, int n_in,
                              void* d_out, int out_size) {
    const float* x  = (const float*)d_in[0];
    const int*   ei = (const int*)d_in[1];     // int32 (JAX x64 disabled)
    const float* W1 = (const float*)d_in[2];
    const float* b1 = (const float*)d_in[3];
    const float* W2 = (const float*)d_in[4];
    const float* b2 = (const float*)d_in[5];
    float* out = (float*)d_out;

    // 1) degrees, dinv+bsum (fused), scan, CSR fill
    k_cnt_zero<<<(N_NODES + 255) / 256, 256>>>();
    k_count<<<(N_EDGES + 255) / 256, 256>>>(ei);
    k_dinv_bsum<<<NB, 256>>>();
    k_scan_bsum<<<1, 256>>>();
    k_rowfill<<<NB, 256>>>();
    k_fill<<<(N_EDGES + 255) / 256, 256>>>(ei);

    // 2) layer 1: pack, fp16 tensor GEMM, CSR gather (writes fp16 A for layer 2)
    {
        size_t tot = (size_t)N_NODES * 64;
        k_pack_x<<<(int)((tot + 255) / 256), 256>>>(x);
        k_pack_W1<<<(512 * D_HID + 255) / 256, 256>>>(W1);
        dim3 grid(D_HID / 128, (N_NODES + 127) / 128);
        k_mma_l1<<<grid, 256>>>();
        k_gather_l1<<<N_NODES, 128>>>(b1);
    }
    // 3) layer 2: pack W2, fp16 tensor GEMM, CSR gather -> d_out
    {
        k_pack_W2<<<(512 * D_OUT + 255) / 256, 256>>>(W2);
        dim3 grid(D_OUT / 128, (N_NODES + 127) / 128);
        k_mma_l2<<<grid, 256>>>();
        k_gather_l2<<<N_NODES, 128>>>(b2, out);
    }
}

// round 14
// speedup vs baseline: 7.3048x; 1.0206x over previous
#include <cuda_runtime.h>
#include <cuda_fp16.h>
#include <cstdint>

#define N_NODES 50000
#define N_EDGES 400000
#define D_IN    512
#define D_HID   512
#define D_OUT   256
#define KP      512    // plain fp16 GEMM
#define NB      196    // scan blocks: 196*256 >= 50000

// ---------------- scratch (device globals; referenced ONLY from device code) ----------------
__device__ __half g_hh  [(size_t)N_NODES * D_HID];  // layer-1 GEMM output (fp16)
__device__ __half g_h2h [(size_t)N_NODES * D_OUT];  // layer-2 GEMM output (fp16)
__device__ float  g_dinv[N_NODES];
__device__ __half g_Ah  [(size_t)N_NODES * KP];     // fp16 A
__device__ __half g_BhT [(size_t)D_HID * KP];       // fp16 B^T, n-major
__device__ int    g_cnt [N_NODES];
__device__ int    g_row [N_NODES + 1];
__device__ int    g_fill[N_NODES];
__device__ int    g_csrc[N_EDGES];
__device__ float  g_cw  [N_EDGES];
__device__ int    g_bsum[256];
__device__ int    g_bpre[256];

// ---------------- degree count ----------------
__global__ void k_cnt_zero() {
    int i = blockIdx.x * blockDim.x + threadIdx.x;
    if (i < N_NODES) g_cnt[i] = 0;
}
__global__ void k_count(const int* __restrict__ ei) {
    int e = blockIdx.x * blockDim.x + threadIdx.x;
    if (e < N_EDGES) atomicAdd(&g_cnt[ei[N_EDGES + e]], 1);
}
__global__ __launch_bounds__(256)
void k_dinv_bsum() {
    __shared__ int sm[256];
    int idx = blockIdx.x * 256 + threadIdx.x;
    int c = 0;
    if (idx < N_NODES) {
        c = g_cnt[idx];
        g_dinv[idx] = rsqrtf(1.0f + (float)c);
    }
    sm[threadIdx.x] = c;
    __syncthreads();
    for (int off = 128; off > 0; off >>= 1) {
        if (threadIdx.x < off) sm[threadIdx.x] += sm[threadIdx.x + off];
        __syncthreads();
    }
    if (threadIdx.x == 0) g_bsum[blockIdx.x] = sm[0];
}
__global__ __launch_bounds__(256)
void k_scan_bsum() {
    __shared__ int sm[256];
    int t = threadIdx.x;
    sm[t] = (t < NB) ? g_bsum[t] : 0;
    __syncthreads();
    for (int off = 1; off < 256; off <<= 1) {
        int v = (t >= off) ? sm[t - off] : 0;
        __syncthreads();
        sm[t] += v;
        __syncthreads();
    }
    int own = (t < NB) ? g_bsum[t] : 0;
    if (t < NB) g_bpre[t] = sm[t] - own;
    if (t == 255) g_row[N_NODES] = sm[255];
}
__global__ __launch_bounds__(256)
void k_rowfill() {
    __shared__ int sm[256];
    int idx = blockIdx.x * 256 + threadIdx.x;
    int t = threadIdx.x;
    int val = (idx < N_NODES) ? g_cnt[idx] : 0;
    sm[t] = val;
    __syncthreads();
    for (int off = 1; off < 256; off <<= 1) {
        int v = (t >= off) ? sm[t - off] : 0;
        __syncthreads();
        sm[t] += v;
        __syncthreads();
    }
    if (idx < N_NODES) {
        int r = g_bpre[blockIdx.x] + sm[t] - val;
        g_row[idx]  = r;
        g_fill[idx] = r;
    }
}
__global__ void k_fill(const int* __restrict__ ei) {
    int e = blockIdx.x * blockDim.x + threadIdx.x;
    if (e < N_EDGES) {
        int s = ei[e];
        int d = ei[N_EDGES + e];
        int pos = atomicAdd(&g_fill[d], 1);
        g_csrc[pos] = s;
        g_cw[pos]   = g_dinv[s] * g_dinv[d];
    }
}

// ---------------- packing ----------------
__global__ void k_pack_x(const float* __restrict__ x) {
    size_t idx = (size_t)blockIdx.x * blockDim.x + threadIdx.x;
    if (idx < (size_t)N_NODES * 64) {
        size_t m = idx >> 6;
        int c8 = (int)(idx & 63) * 8;
        const float* src = x + m * 512 + c8;
        float4 v0 = *(const float4*)src;
        float4 v1 = *(const float4*)(src + 4);
        __half2 h[4] = {
            __floats2half2_rn(v0.x, v0.y), __floats2half2_rn(v0.z, v0.w),
            __floats2half2_rn(v1.x, v1.y), __floats2half2_rn(v1.z, v1.w) };
        *(uint4*)(g_Ah + m * KP + c8) = *(uint4*)h;
    }
}
template <int N>
__device__ __forceinline__
void packB_body(const float* __restrict__ W) {
    int idx = blockIdx.x * blockDim.x + threadIdx.x;
    if (idx < 512 * N) {
        int k = idx / N, n = idx % N;
        g_BhT[(size_t)n * KP + k] = __float2half(W[idx]);
    }
}
__global__ void k_pack_W1(const float* __restrict__ W) { packB_body<D_HID>(W); }
__global__ void k_pack_W2(const float* __restrict__ W) { packB_body<D_OUT>(W); }

// ---------------- mma.sync m16n8k16 + ldmatrix ----------------
__device__ __forceinline__
void mma16816(float* d, const uint32_t* a, const uint32_t* b) {
    asm volatile(
        "mma.sync.aligned.m16n8k16.row.col.f32.f16.f16.f32 "
        "{%0,%1,%2,%3}, {%4,%5,%6,%7}, {%8,%9}, {%0,%1,%2,%3};\n"
        : "+f"(d[0]), "+f"(d[1]), "+f"(d[2]), "+f"(d[3])
        : "r"(a[0]), "r"(a[1]), "r"(a[2]), "r"(a[3]),
          "r"(b[0]), "r"(b[1]));
}
__device__ __forceinline__
void ldsm_x4(uint32_t* r, uint32_t addr) {
    asm volatile("ldmatrix.sync.aligned.m8n8.x4.shared.b16 {%0,%1,%2,%3}, [%4];"
                 : "=r"(r[0]), "=r"(r[1]), "=r"(r[2]), "=r"(r[3]) : "r"(addr));
}
__device__ __forceinline__
void ldsm_x2(uint32_t* r, uint32_t addr) {
    asm volatile("ldmatrix.sync.aligned.m8n8.x2.shared.b16 {%0,%1}, [%2];"
                 : "=r"(r[0]), "=r"(r[1]) : "r"(addr));
}
__device__ __forceinline__ uint32_t smem_u32(const void* p) {
    uint32_t a;
    asm("{ .reg .u64 t; cvta.to.shared.u64 t, %1; cvt.u32.u64 %0, t; }"
        : "=r"(a) : "l"(p));
    return a;
}

// ---------------- tensor-core GEMM: Ch[M,N] = half(A[M,512] @ B[512,N]) ----------------
// 128x128 block tile, BK=32, 256 threads (8 warps, 2x4), warp tile 64x32,
// double-buffered smem, ldmatrix fragment loads.
template <int N>
__device__ __forceinline__
void gemm_mma_body(const __half* __restrict__ Ah, const __half* __restrict__ BhT,
                   __half* __restrict__ Ch) {
    constexpr int BM = 128, BK = 32, PITCH = 40;
    __shared__ __half As[2][BM][PITCH];
    __shared__ __half Bs[2][BM][PITCH];

    const int tid  = threadIdx.x;
    const int lane = tid & 31;
    const int wid  = tid >> 5;
    const int warp_m = wid >> 2;
    const int warp_n = wid & 3;
    const int rowBase = blockIdx.y * BM;
    const int colBase = blockIdx.x * BM;

    const int lg  = lane >> 2;
    const int lc2 = (lane & 3) * 2;

    // ldmatrix per-lane source coordinates (within warp tile)
    const int rA = warp_m * 64 + (lane & 15);            // A: row for .x4
    const int cA = (lane >> 4) * 8;                      // A: col offset 0/8
    const int rB = warp_n * 32 + (lane & 7);             // B: row for .x2
    const int cB = ((lane >> 3) & 1) * 8;                // B: col offset 0/8 (lanes>=16 ignored)

    const int r0 = tid >> 2,  s0 = (tid & 3) * 8;
    const int r1 = r0 + 64;
    const uint4 z4 = make_uint4(0, 0, 0, 0);

    float acc[4][4][4];
    #pragma unroll
    for (int i = 0; i < 4; i++)
        #pragma unroll
        for (int j = 0; j < 4; j++)
            #pragma unroll
            for (int q = 0; q < 4; q++) acc[i][j][q] = 0.0f;

    uint4 na0, na1, nb0, nb1;
    {
        int gm0 = rowBase + r0, gm1 = rowBase + r1;
        na0 = (gm0 < N_NODES) ? *(const uint4*)(Ah + (size_t)gm0 * KP + s0) : z4;
        na1 = (gm1 < N_NODES) ? *(const uint4*)(Ah + (size_t)gm1 * KP + s0) : z4;
        nb0 = *(const uint4*)(BhT + (size_t)(colBase + r0) * KP + s0);
        nb1 = *(const uint4*)(BhT + (size_t)(colBase + r1) * KP + s0);
        *(uint4*)&As[0][r0][s0] = na0;
        *(uint4*)&As[0][r1][s0] = na1;
        *(uint4*)&Bs[0][r0][s0] = nb0;
        *(uint4*)&Bs[0][r1][s0] = nb1;
    }
    __syncthreads();

    constexpr int NIT = KP / BK;   // 16
    for (int t = 0; t < NIT; t++) {
        const int buf = t & 1;

        if (t + 1 < NIT) {
            const int k0 = (t + 1) * BK;
            int gm0 = rowBase + r0, gm1 = rowBase + r1;
            na0 = (gm0 < N_NODES) ? *(const uint4*)(Ah + (size_t)gm0 * KP + k0 + s0) : z4;
            na1 = (gm1 < N_NODES) ? *(const uint4*)(Ah + (size_t)gm1 * KP + k0 + s0) : z4;
            nb0 = *(const uint4*)(BhT + (size_t)(colBase + r0) * KP + k0 + s0);
            nb1 = *(const uint4*)(BhT + (size_t)(colBase + r1) * KP + k0 + s0);
        }

        #pragma unroll
        for (int ks = 0; ks < 2; ks++) {
            const int c = ks * 16;
            uint32_t afr[4][4], bfr[4][2];
            #pragma unroll
            for (int mf = 0; mf < 4; mf++)
                ldsm_x4(afr[mf], smem_u32(&As[buf][rA + mf * 16][c + cA]));
            #pragma unroll
            for (int nf = 0; nf < 4; nf++)
                ldsm_x2(bfr[nf], smem_u32(&Bs[buf][rB + nf * 8][c + cB]));
            #pragma unroll
            for (int mf = 0; mf < 4; mf++)
                #pragma unroll
                for (int nf = 0; nf < 4; nf++)
                    mma16816(acc[mf][nf], afr[mf], bfr[nf]);
        }

        if (t + 1 < NIT) {
            const int nbuf = buf ^ 1;
            *(uint4*)&As[nbuf][r0][s0] = na0;
            *(uint4*)&As[nbuf][r1][s0] = na1;
            *(uint4*)&Bs[nbuf][r0][s0] = nb0;
            *(uint4*)&Bs[nbuf][r1][s0] = nb1;
        }
        __syncthreads();
    }

    #pragma unroll
    for (int mf = 0; mf < 4; mf++) {
        #pragma unroll
        for (int hh = 0; hh < 2; hh++) {
            int m = rowBase + warp_m * 64 + mf * 16 + lg + hh * 8;
            if (m < N_NODES) {
                #pragma unroll
                for (int nf = 0; nf < 4; nf++) {
                    int n = colBase + warp_n * 32 + nf * 8 + lc2;
                    *(__half2*)(Ch + (size_t)m * N + n) =
                        __floats2half2_rn(acc[mf][nf][hh * 2 + 0], acc[mf][nf][hh * 2 + 1]);
                }
            }
        }
    }
}

__global__ __launch_bounds__(256)
void k_mma_l1() { gemm_mma_body<D_HID>(g_Ah, g_BhT, g_hh); }
__global__ __launch_bounds__(256)
void k_mma_l2() { gemm_mma_body<D_OUT>(g_Ah, g_BhT, g_h2h); }

// ---------------- CSR gather layer 1 (4-wide edge unroll): writes fp16 A ----------------
__global__ __launch_bounds__(128)
void k_gather_l1(const float* __restrict__ b1) {
    int i = blockIdx.x;
    int col = threadIdx.x * 4;
    float s = g_dinv[i];
    float ss = s * s;

    __half2 hv2[2];
    *(uint2*)hv2 = *(const uint2*)(g_hh + (size_t)i * D_HID + col);
    float2 h0 = __half22float2(hv2[0]);
    float2 h1 = __half22float2(hv2[1]);
    float4 bv = *(const float4*)(b1 + col);
    float4 acc = make_float4(fmaf(h0.x, ss, bv.x), fmaf(h0.y, ss, bv.y),
                             fmaf(h1.x, ss, bv.z), fmaf(h1.y, ss, bv.w));

    int beg = g_row[i], end = g_row[i + 1];
    int j = beg;
    for (; j + 3 < end; j += 4) {
        int   s0 = g_csrc[j],     s1 = g_csrc[j + 1];
        int   s2 = g_csrc[j + 2], s3 = g_csrc[j + 3];
        float w0 = g_cw[j],       w1 = g_cw[j + 1];
        float w2 = g_cw[j + 2],   w3 = g_cw[j + 3];
        uint2 r0 = *(const uint2*)(g_hh + (size_t)s0 * D_HID + col);
        uint2 r1 = *(const uint2*)(g_hh + (size_t)s1 * D_HID + col);
        uint2 r2 = *(const uint2*)(g_hh + (size_t)s2 * D_HID + col);
        uint2 r3 = *(const uint2*)(g_hh + (size_t)s3 * D_HID + col);
        const __half2* p0 = (const __half2*)&r0;
        const __half2* p1 = (const __half2*)&r1;
        const __half2* p2 = (const __half2*)&r2;
        const __half2* p3 = (const __half2*)&r3;
        float2 a;
        a = __half22float2(p0[0]); acc.x = fmaf(a.x, w0, acc.x); acc.y = fmaf(a.y, w0, acc.y);
        a = __half22float2(p0[1]); acc.z = fmaf(a.x, w0, acc.z); acc.w = fmaf(a.y, w0, acc.w);
        a = __half22float2(p1[0]); acc.x = fmaf(a.x, w1, acc.x); acc.y = fmaf(a.y, w1, acc.y);
        a = __half22float2(p1[1]); acc.z = fmaf(a.x, w1, acc.z); acc.w = fmaf(a.y, w1, acc.w);
        a = __half22float2(p2[0]); acc.x = fmaf(a.x, w2, acc.x); acc.y = fmaf(a.y, w2, acc.y);
        a = __half22float2(p2[1]); acc.z = fmaf(a.x, w2, acc.z); acc.w = fmaf(a.y, w2, acc.w);
        a = __half22float2(p3[0]); acc.x = fmaf(a.x, w3, acc.x); acc.y = fmaf(a.y, w3, acc.y);
        a = __half22float2(p3[1]); acc.z = fmaf(a.x, w3, acc.z); acc.w = fmaf(a.y, w3, acc.w);
    }
    for (; j < end; j++) {
        int   sj = g_csrc[j];
        float w  = g_cw[j];
        uint2 r = *(const uint2*)(g_hh + (size_t)sj * D_HID + col);
        const __half2* p = (const __half2*)&r;
        float2 a0 = __half22float2(p[0]);
        float2 a1 = __half22float2(p[1]);
        acc.x = fmaf(a0.x, w, acc.x);
        acc.y = fmaf(a0.y, w, acc.y);
        acc.z = fmaf(a1.x, w, acc.z);
        acc.w = fmaf(a1.y, w, acc.w);
    }
    acc.x = fmaxf(acc.x, 0.f); acc.y = fmaxf(acc.y, 0.f);
    acc.z = fmaxf(acc.z, 0.f); acc.w = fmaxf(acc.w, 0.f);

    __half2 h[2] = { __floats2half2_rn(acc.x, acc.y),
                     __floats2half2_rn(acc.z, acc.w) };
    *(uint2*)(g_Ah + (size_t)i * KP + col) = *(uint2*)h;
}

// ---------------- CSR gather layer 2 (4-wide edge unroll) -> out (fp32) ----------------
__global__ __launch_bounds__(128)
void k_gather_l2(const float* __restrict__ b2, float* __restrict__ out) {
    int i = blockIdx.x;
    int col = threadIdx.x * 2;
    float s = g_dinv[i];
    float ss = s * s;

    float2 hv = __half22float2(*(const __half2*)(g_h2h + (size_t)i * D_OUT + col));
    float2 bv = *(const float2*)(b2 + col);
    float2 acc = make_float2(fmaf(hv.x, ss, bv.x), fmaf(hv.y, ss, bv.y));

    int beg = g_row[i], end = g_row[i + 1];
    int j = beg;
    for (; j + 3 < end; j += 4) {
        int   s0 = g_csrc[j],     s1 = g_csrc[j + 1];
        int   s2 = g_csrc[j + 2], s3 = g_csrc[j + 3];
        float w0 = g_cw[j],       w1 = g_cw[j + 1];
        float w2 = g_cw[j + 2],   w3 = g_cw[j + 3];
        __half2 q0 = *(const __half2*)(g_h2h + (size_t)s0 * D_OUT + col);
        __half2 q1 = *(const __half2*)(g_h2h + (size_t)s1 * D_OUT + col);
        __half2 q2 = *(const __half2*)(g_h2h + (size_t)s2 * D_OUT + col);
        __half2 q3 = *(const __half2*)(g_h2h + (size_t)s3 * D_OUT + col);
        float2 a;
        a = __half22float2(q0); acc.x = fmaf(a.x, w0, acc.x); acc.y = fmaf(a.y, w0, acc.y);
        a = __half22float2(q1); acc.x = fmaf(a.x, w1, acc.x); acc.y = fmaf(a.y, w1, acc.y);
        a = __half22float2(q2); acc.x = fmaf(a.x, w2, acc.x); acc.y = fmaf(a.y, w2, acc.y);
        a = __half22float2(q3); acc.x = fmaf(a.x, w3, acc.x); acc.y = fmaf(a.y, w3, acc.y);
    }
    for (; j < end; j++) {
        int   sj = g_csrc[j];
        float w  = g_cw[j];
        float2 a = __half22float2(*(const __half2*)(g_h2h + (size_t)sj * D_OUT + col));
        acc.x = fmaf(a.x, w, acc.x);
        acc.y = fmaf(a.y, w, acc.y);
    }
    *(float2*)(out + (size_t)i * D_OUT + col) = acc;
}

// ---------------- launch ----------------
extern "C" void kernel_launch(void* const* d_in, const int* in_sizes, int n_in,
                              void* d_out, int out_size) {
    const float* x  = (const float*)d_in[0];
    const int*   ei = (const int*)d_in[1];     // int32 (JAX x64 disabled)
    const float* W1 = (const float*)d_in[2];
    const float* b1 = (const float*)d_in[3];
    const float* W2 = (const float*)d_in[4];
    const float* b2 = (const float*)d_in[5];
    float* out = (float*)d_out;

    // 1) degrees, dinv+bsum (fused), scan, CSR fill
    k_cnt_zero<<<(N_NODES + 255) / 256, 256>>>();
    k_count<<<(N_EDGES + 255) / 256, 256>>>(ei);
    k_dinv_bsum<<<NB, 256>>>();
    k_scan_bsum<<<1, 256>>>();
    k_rowfill<<<NB, 256>>>();
    k_fill<<<(N_EDGES + 255) / 256, 256>>>(ei);

    // 2) layer 1: pack, fp16 tensor GEMM (ldmatrix), CSR gather (writes fp16 A)
    {
        size_t tot = (size_t)N_NODES * 64;
        k_pack_x<<<(int)((tot + 255) / 256), 256>>>(x);
        k_pack_W1<<<(512 * D_HID + 255) / 256, 256>>>(W1);
        dim3 grid(D_HID / 128, (N_NODES + 127) / 128);
        k_mma_l1<<<grid, 256>>>();
        k_gather_l1<<<N_NODES, 128>>>(b1);
    }
    // 3) layer 2: pack W2, fp16 tensor GEMM, CSR gather -> d_out
    {
        k_pack_W2<<<(512 * D_OUT + 255) / 256, 256>>>(W2);
        dim3 grid(D_OUT / 128, (N_NODES + 127) / 128);
        k_mma_l2<<<grid, 256>>>();
        k_gather_l2<<<N_NODES, 128>>>(b2, out);
    }
}

// round 15
// speedup vs baseline: 7.6198x; 1.0431x over previous
#include <cuda_runtime.h>
#include <cuda_fp16.h>
#include <cstdint>

#define N_NODES 50000
#define N_EDGES 400000
#define D_IN    512
#define D_HID   512
#define D_OUT   256
#define KP      512    // plain fp16 GEMM
#define NB      196    // scan blocks: 196*256 >= 50000

// ---------------- scratch (device globals; referenced ONLY from device code) ----------------
__device__ __half g_hh  [(size_t)N_NODES * D_HID];  // layer-1 GEMM output (fp16)
__device__ __half g_h2h [(size_t)N_NODES * D_OUT];  // layer-2 GEMM output (fp16)
__device__ float  g_dinv[N_NODES];
__device__ __half g_Ah  [(size_t)N_NODES * KP];     // fp16 A
__device__ __half g_BhT [(size_t)D_HID * KP];       // fp16 B^T, n-major
__device__ int    g_cnt [N_NODES];
__device__ int    g_row [N_NODES + 1];
__device__ int    g_fill[N_NODES];
__device__ int    g_csrc[N_EDGES];
__device__ float  g_cw  [N_EDGES];
__device__ int    g_bsum[256];
__device__ int    g_bpre[256];

// ---------------- side stream + events (created once at static init; no device memory) ----
static cudaStream_t s_side = 0;
static cudaEvent_t  s_ev_fork = 0, s_ev_join = 0;
namespace {
struct SideInit {
    SideInit() {
        if (cudaStreamCreateWithFlags(&s_side, cudaStreamNonBlocking) != cudaSuccess)
            s_side = 0;
        if (cudaEventCreateWithFlags(&s_ev_fork, cudaEventDisableTiming) != cudaSuccess)
            s_ev_fork = 0;
        if (cudaEventCreateWithFlags(&s_ev_join, cudaEventDisableTiming) != cudaSuccess)
            s_ev_join = 0;
    }
};
static SideInit s_side_init;
}

// ---------------- degree count ----------------
__global__ void k_cnt_zero() {
    int i = blockIdx.x * blockDim.x + threadIdx.x;
    if (i < N_NODES) g_cnt[i] = 0;
}
__global__ void k_count(const int* __restrict__ ei) {
    int e = blockIdx.x * blockDim.x + threadIdx.x;
    if (e < N_EDGES) atomicAdd(&g_cnt[ei[N_EDGES + e]], 1);
}
__global__ __launch_bounds__(256)
void k_dinv_bsum() {
    __shared__ int sm[256];
    int idx = blockIdx.x * 256 + threadIdx.x;
    int c = 0;
    if (idx < N_NODES) {
        c = g_cnt[idx];
        g_dinv[idx] = rsqrtf(1.0f + (float)c);
    }
    sm[threadIdx.x] = c;
    __syncthreads();
    for (int off = 128; off > 0; off >>= 1) {
        if (threadIdx.x < off) sm[threadIdx.x] += sm[threadIdx.x + off];
        __syncthreads();
    }
    if (threadIdx.x == 0) g_bsum[blockIdx.x] = sm[0];
}
__global__ __launch_bounds__(256)
void k_scan_bsum() {
    __shared__ int sm[256];
    int t = threadIdx.x;
    sm[t] = (t < NB) ? g_bsum[t] : 0;
    __syncthreads();
    for (int off = 1; off < 256; off <<= 1) {
        int v = (t >= off) ? sm[t - off] : 0;
        __syncthreads();
        sm[t] += v;
        __syncthreads();
    }
    int own = (t < NB) ? g_bsum[t] : 0;
    if (t < NB) g_bpre[t] = sm[t] - own;
    if (t == 255) g_row[N_NODES] = sm[255];
}
__global__ __launch_bounds__(256)
void k_rowfill() {
    __shared__ int sm[256];
    int idx = blockIdx.x * 256 + threadIdx.x;
    int t = threadIdx.x;
    int val = (idx < N_NODES) ? g_cnt[idx] : 0;
    sm[t] = val;
    __syncthreads();
    for (int off = 1; off < 256; off <<= 1) {
        int v = (t >= off) ? sm[t - off] : 0;
        __syncthreads();
        sm[t] += v;
        __syncthreads();
    }
    if (idx < N_NODES) {
        int r = g_bpre[blockIdx.x] + sm[t] - val;
        g_row[idx]  = r;
        g_fill[idx] = r;
    }
}
__global__ void k_fill(const int* __restrict__ ei) {
    int e = blockIdx.x * blockDim.x + threadIdx.x;
    if (e < N_EDGES) {
        int s = ei[e];
        int d = ei[N_EDGES + e];
        int pos = atomicAdd(&g_fill[d], 1);
        g_csrc[pos] = s;
        g_cw[pos]   = g_dinv[s] * g_dinv[d];
    }
}

// ---------------- packing ----------------
__global__ void k_pack_x(const float* __restrict__ x) {
    size_t idx = (size_t)blockIdx.x * blockDim.x + threadIdx.x;
    if (idx < (size_t)N_NODES * 64) {
        size_t m = idx >> 6;
        int c8 = (int)(idx & 63) * 8;
        const float* src = x + m * 512 + c8;
        float4 v0 = *(const float4*)src;
        float4 v1 = *(const float4*)(src + 4);
        __half2 h[4] = {
            __floats2half2_rn(v0.x, v0.y), __floats2half2_rn(v0.z, v0.w),
            __floats2half2_rn(v1.x, v1.y), __floats2half2_rn(v1.z, v1.w) };
        *(uint4*)(g_Ah + m * KP + c8) = *(uint4*)h;
    }
}
template <int N>
__device__ __forceinline__
void packB_body(const float* __restrict__ W) {
    int idx = blockIdx.x * blockDim.x + threadIdx.x;
    if (idx < 512 * N) {
        int k = idx / N, n = idx % N;
        g_BhT[(size_t)n * KP + k] = __float2half(W[idx]);
    }
}
__global__ void k_pack_W1(const float* __restrict__ W) { packB_body<D_HID>(W); }
__global__ void k_pack_W2(const float* __restrict__ W) { packB_body<D_OUT>(W); }

// ---------------- mma.sync m16n8k16 + ldmatrix ----------------
__device__ __forceinline__
void mma16816(float* d, const uint32_t* a, const uint32_t* b) {
    asm volatile(
        "mma.sync.aligned.m16n8k16.row.col.f32.f16.f16.f32 "
        "{%0,%1,%2,%3}, {%4,%5,%6,%7}, {%8,%9}, {%0,%1,%2,%3};\n"
        : "+f"(d[0]), "+f"(d[1]), "+f"(d[2]), "+f"(d[3])
        : "r"(a[0]), "r"(a[1]), "r"(a[2]), "r"(a[3]),
          "r"(b[0]), "r"(b[1]));
}
__device__ __forceinline__
void ldsm_x4(uint32_t* r, uint32_t addr) {
    asm volatile("ldmatrix.sync.aligned.m8n8.x4.shared.b16 {%0,%1,%2,%3}, [%4];"
                 : "=r"(r[0]), "=r"(r[1]), "=r"(r[2]), "=r"(r[3]) : "r"(addr));
}
__device__ __forceinline__
void ldsm_x2(uint32_t* r, uint32_t addr) {
    asm volatile("ldmatrix.sync.aligned.m8n8.x2.shared.b16 {%0,%1}, [%2];"
                 : "=r"(r[0]), "=r"(r[1]) : "r"(addr));
}
__device__ __forceinline__ uint32_t smem_u32(const void* p) {
    uint32_t a;
    asm("{ .reg .u64 t; cvta.to.shared.u64 t, %1; cvt.u32.u64 %0, t; }"
        : "=r"(a) : "l"(p));
    return a;
}

// ---------------- tensor-core GEMM: Ch[M,N] = half(A[M,512] @ B[512,N]) ----------------
template <int N>
__device__ __forceinline__
void gemm_mma_body(const __half* __restrict__ Ah, const __half* __restrict__ BhT,
                   __half* __restrict__ Ch) {
    constexpr int BM = 128, BK = 32, PITCH = 40;
    __shared__ __half As[2][BM][PITCH];
    __shared__ __half Bs[2][BM][PITCH];

    const int tid  = threadIdx.x;
    const int lane = tid & 31;
    const int wid  = tid >> 5;
    const int warp_m = wid >> 2;
    const int warp_n = wid & 3;
    const int rowBase = blockIdx.y * BM;
    const int colBase = blockIdx.x * BM;

    const int lg  = lane >> 2;
    const int lc2 = (lane & 3) * 2;

    const int rA = warp_m * 64 + (lane & 15);
    const int cA = (lane >> 4) * 8;
    const int rB = warp_n * 32 + (lane & 7);
    const int cB = ((lane >> 3) & 1) * 8;

    const int r0 = tid >> 2,  s0 = (tid & 3) * 8;
    const int r1 = r0 + 64;
    const uint4 z4 = make_uint4(0, 0, 0, 0);

    float acc[4][4][4];
    #pragma unroll
    for (int i = 0; i < 4; i++)
        #pragma unroll
        for (int j = 0; j < 4; j++)
            #pragma unroll
            for (int q = 0; q < 4; q++) acc[i][j][q] = 0.0f;

    uint4 na0, na1, nb0, nb1;
    {
        int gm0 = rowBase + r0, gm1 = rowBase + r1;
        na0 = (gm0 < N_NODES) ? *(const uint4*)(Ah + (size_t)gm0 * KP + s0) : z4;
        na1 = (gm1 < N_NODES) ? *(const uint4*)(Ah + (size_t)gm1 * KP + s0) : z4;
        nb0 = *(const uint4*)(BhT + (size_t)(colBase + r0) * KP + s0);
        nb1 = *(const uint4*)(BhT + (size_t)(colBase + r1) * KP + s0);
        *(uint4*)&As[0][r0][s0] = na0;
        *(uint4*)&As[0][r1][s0] = na1;
        *(uint4*)&Bs[0][r0][s0] = nb0;
        *(uint4*)&Bs[0][r1][s0] = nb1;
    }
    __syncthreads();

    constexpr int NIT = KP / BK;   // 16
    for (int t = 0; t < NIT; t++) {
        const int buf = t & 1;

        if (t + 1 < NIT) {
            const int k0 = (t + 1) * BK;
            int gm0 = rowBase + r0, gm1 = rowBase + r1;
            na0 = (gm0 < N_NODES) ? *(const uint4*)(Ah + (size_t)gm0 * KP + k0 + s0) : z4;
            na1 = (gm1 < N_NODES) ? *(const uint4*)(Ah + (size_t)gm1 * KP + k0 + s0) : z4;
            nb0 = *(const uint4*)(BhT + (size_t)(colBase + r0) * KP + k0 + s0);
            nb1 = *(const uint4*)(BhT + (size_t)(colBase + r1) * KP + k0 + s0);
        }

        #pragma unroll
        for (int ks = 0; ks < 2; ks++) {
            const int c = ks * 16;
            uint32_t afr[4][4], bfr[4][2];
            #pragma unroll
            for (int mf = 0; mf < 4; mf++)
                ldsm_x4(afr[mf], smem_u32(&As[buf][rA + mf * 16][c + cA]));
            #pragma unroll
            for (int nf = 0; nf < 4; nf++)
                ldsm_x2(bfr[nf], smem_u32(&Bs[buf][rB + nf * 8][c + cB]));
            #pragma unroll
            for (int mf = 0; mf < 4; mf++)
                #pragma unroll
                for (int nf = 0; nf < 4; nf++)
                    mma16816(acc[mf][nf], afr[mf], bfr[nf]);
        }

        if (t + 1 < NIT) {
            const int nbuf = buf ^ 1;
            *(uint4*)&As[nbuf][r0][s0] = na0;
            *(uint4*)&As[nbuf][r1][s0] = na1;
            *(uint4*)&Bs[nbuf][r0][s0] = nb0;
            *(uint4*)&Bs[nbuf][r1][s0] = nb1;
        }
        __syncthreads();
    }

    #pragma unroll
    for (int mf = 0; mf < 4; mf++) {
        #pragma unroll
        for (int hh = 0; hh < 2; hh++) {
            int m = rowBase + warp_m * 64 + mf * 16 + lg + hh * 8;
            if (m < N_NODES) {
                #pragma unroll
                for (int nf = 0; nf < 4; nf++) {
                    int n = colBase + warp_n * 32 + nf * 8 + lc2;
                    *(__half2*)(Ch + (size_t)m * N + n) =
                        __floats2half2_rn(acc[mf][nf][hh * 2 + 0], acc[mf][nf][hh * 2 + 1]);
                }
            }
        }
    }
}

__global__ __launch_bounds__(256)
void k_mma_l1() { gemm_mma_body<D_HID>(g_Ah, g_BhT, g_hh); }
__global__ __launch_bounds__(256)
void k_mma_l2() { gemm_mma_body<D_OUT>(g_Ah, g_BhT, g_h2h); }

// ---------------- CSR gather layer 1 (4-wide edge unroll): writes fp16 A ----------------
__global__ __launch_bounds__(128)
void k_gather_l1(const float* __restrict__ b1) {
    int i = blockIdx.x;
    int col = threadIdx.x * 4;
    float s = g_dinv[i];
    float ss = s * s;

    __half2 hv2[2];
    *(uint2*)hv2 = *(const uint2*)(g_hh + (size_t)i * D_HID + col);
    float2 h0 = __half22float2(hv2[0]);
    float2 h1 = __half22float2(hv2[1]);
    float4 bv = *(const float4*)(b1 + col);
    float4 acc = make_float4(fmaf(h0.x, ss, bv.x), fmaf(h0.y, ss, bv.y),
                             fmaf(h1.x, ss, bv.z), fmaf(h1.y, ss, bv.w));

    int beg = g_row[i], end = g_row[i + 1];
    int j = beg;
    for (; j + 3 < end; j += 4) {
        int   s0 = g_csrc[j],     s1 = g_csrc[j + 1];
        int   s2 = g_csrc[j + 2], s3 = g_csrc[j + 3];
        float w0 = g_cw[j],       w1 = g_cw[j + 1];
        float w2 = g_cw[j + 2],   w3 = g_cw[j + 3];
        uint2 r0 = *(const uint2*)(g_hh + (size_t)s0 * D_HID + col);
        uint2 r1 = *(const uint2*)(g_hh + (size_t)s1 * D_HID + col);
        uint2 r2 = *(const uint2*)(g_hh + (size_t)s2 * D_HID + col);
        uint2 r3 = *(const uint2*)(g_hh + (size_t)s3 * D_HID + col);
        const __half2* p0 = (const __half2*)&r0;
        const __half2* p1 = (const __half2*)&r1;
        const __half2* p2 = (const __half2*)&r2;
        const __half2* p3 = (const __half2*)&r3;
        float2 a;
        a = __half22float2(p0[0]); acc.x = fmaf(a.x, w0, acc.x); acc.y = fmaf(a.y, w0, acc.y);
        a = __half22float2(p0[1]); acc.z = fmaf(a.x, w0, acc.z); acc.w = fmaf(a.y, w0, acc.w);
        a = __half22float2(p1[0]); acc.x = fmaf(a.x, w1, acc.x); acc.y = fmaf(a.y, w1, acc.y);
        a = __half22float2(p1[1]); acc.z = fmaf(a.x, w1, acc.z); acc.w = fmaf(a.y, w1, acc.w);
        a = __half22float2(p2[0]); acc.x = fmaf(a.x, w2, acc.x); acc.y = fmaf(a.y, w2, acc.y);
        a = __half22float2(p2[1]); acc.z = fmaf(a.x, w2, acc.z); acc.w = fmaf(a.y, w2, acc.w);
        a = __half22float2(p3[0]); acc.x = fmaf(a.x, w3, acc.x); acc.y = fmaf(a.y, w3, acc.y);
        a = __half22float2(p3[1]); acc.z = fmaf(a.x, w3, acc.z); acc.w = fmaf(a.y, w3, acc.w);
    }
    for (; j < end; j++) {
        int   sj = g_csrc[j];
        float w  = g_cw[j];
        uint2 r = *(const uint2*)(g_hh + (size_t)sj * D_HID + col);
        const __half2* p = (const __half2*)&r;
        float2 a0 = __half22float2(p[0]);
        float2 a1 = __half22float2(p[1]);
        acc.x = fmaf(a0.x, w, acc.x);
        acc.y = fmaf(a0.y, w, acc.y);
        acc.z = fmaf(a1.x, w, acc.z);
        acc.w = fmaf(a1.y, w, acc.w);
    }
    acc.x = fmaxf(acc.x, 0.f); acc.y = fmaxf(acc.y, 0.f);
    acc.z = fmaxf(acc.z, 0.f); acc.w = fmaxf(acc.w, 0.f);

    __half2 h[2] = { __floats2half2_rn(acc.x, acc.y),
                     __floats2half2_rn(acc.z, acc.w) };
    *(uint2*)(g_Ah + (size_t)i * KP + col) = *(uint2*)h;
}

// ---------------- CSR gather layer 2 (4-wide edge unroll) -> out (fp32) ----------------
__global__ __launch_bounds__(128)
void k_gather_l2(const float* __restrict__ b2, float* __restrict__ out) {
    int i = blockIdx.x;
    int col = threadIdx.x * 2;
    float s = g_dinv[i];
    float ss = s * s;

    float2 hv = __half22float2(*(const __half2*)(g_h2h + (size_t)i * D_OUT + col));
    float2 bv = *(const float2*)(b2 + col);
    float2 acc = make_float2(fmaf(hv.x, ss, bv.x), fmaf(hv.y, ss, bv.y));

    int beg = g_row[i], end = g_row[i + 1];
    int j = beg;
    for (; j + 3 < end; j += 4) {
        int   s0 = g_csrc[j],     s1 = g_csrc[j + 1];
        int   s2 = g_csrc[j + 2], s3 = g_csrc[j + 3];
        float w0 = g_cw[j],       w1 = g_cw[j + 1];
        float w2 = g_cw[j + 2],   w3 = g_cw[j + 3];
        __half2 q0 = *(const __half2*)(g_h2h + (size_t)s0 * D_OUT + col);
        __half2 q1 = *(const __half2*)(g_h2h + (size_t)s1 * D_OUT + col);
        __half2 q2 = *(const __half2*)(g_h2h + (size_t)s2 * D_OUT + col);
        __half2 q3 = *(const __half2*)(g_h2h + (size_t)s3 * D_OUT + col);
        float2 a;
        a = __half22float2(q0); acc.x = fmaf(a.x, w0, acc.x); acc.y = fmaf(a.y, w0, acc.y);
        a = __half22float2(q1); acc.x = fmaf(a.x, w1, acc.x); acc.y = fmaf(a.y, w1, acc.y);
        a = __half22float2(q2); acc.x = fmaf(a.x, w2, acc.x); acc.y = fmaf(a.y, w2, acc.y);
        a = __half22float2(q3); acc.x = fmaf(a.x, w3, acc.x); acc.y = fmaf(a.y, w3, acc.y);
    }
    for (; j < end; j++) {
        int   sj = g_csrc[j];
        float w  = g_cw[j];
        float2 a = __half22float2(*(const __half2*)(g_h2h + (size_t)sj * D_OUT + col));
        acc.x = fmaf(a.x, w, acc.x);
        acc.y = fmaf(a.y, w, acc.y);
    }
    *(float2*)(out + (size_t)i * D_OUT + col) = acc;
}

// ---------------- launch ----------------
extern "C" void kernel_launch(void* const* d_in, const int* in_sizes, int n_in,
                              void* d_out, int out_size) {
    const float* x  = (const float*)d_in[0];
    const int*   ei = (const int*)d_in[1];     // int32 (JAX x64 disabled)
    const float* W1 = (const float*)d_in[2];
    const float* b1 = (const float*)d_in[3];
    const float* W2 = (const float*)d_in[4];
    const float* b2 = (const float*)d_in[5];
    float* out = (float*)d_out;

    const bool fork = (s_side != 0 && s_ev_fork != 0 && s_ev_join != 0);
    cudaStream_t side = fork ? s_side : 0;

    if (fork) {
        // fork: side stream depends on capture-stream start
        cudaEventRecord(s_ev_fork, 0);
        cudaStreamWaitEvent(side, s_ev_fork, 0);
    }

    // ---- side stream: CSR build (independent of packs/GEMM1) ----
    k_cnt_zero<<<(N_NODES + 255) / 256, 256, 0, side>>>();
    k_count<<<(N_EDGES + 255) / 256, 256, 0, side>>>(ei);
    k_dinv_bsum<<<NB, 256, 0, side>>>();
    k_scan_bsum<<<1, 256, 0, side>>>();
    k_rowfill<<<NB, 256, 0, side>>>();
    k_fill<<<(N_EDGES + 255) / 256, 256, 0, side>>>(ei);
    if (fork) cudaEventRecord(s_ev_join, side);

    // ---- main stream: pack + GEMM layer 1 ----
    {
        size_t tot = (size_t)N_NODES * 64;
        k_pack_x<<<(int)((tot + 255) / 256), 256>>>(x);
        k_pack_W1<<<(512 * D_HID + 255) / 256, 256>>>(W1);
        dim3 grid(D_HID / 128, (N_NODES + 127) / 128);
        k_mma_l1<<<grid, 256>>>();
    }

    // join: gather_l1 needs CSR (row/csrc/cw) + dinv
    if (fork) cudaStreamWaitEvent(0, s_ev_join, 0);

    k_gather_l1<<<N_NODES, 128>>>(b1);

    // layer 2
    k_pack_W2<<<(512 * D_OUT + 255) / 256, 256>>>(W2);
    {
        dim3 grid(D_OUT / 128, (N_NODES + 127) / 128);
        k_mma_l2<<<grid, 256>>>();
    }
    k_gather_l2<<<N_NODES, 128>>>(b2, out);
}

// round 16
// speedup vs baseline: 7.6376x; 1.0023x over previous
#include <cuda_runtime.h>
#include <cuda_fp16.h>
#include <cstdint>

#define N_NODES 50000
#define N_EDGES 400000
#define D_IN    512
#define D_HID   512
#define D_OUT   256
#define KP      512    // plain fp16 GEMM
#define NB      196    // scan blocks: 196*256 >= 50000

// ---------------- scratch (device globals; referenced ONLY from device code) ----------------
__device__ __half g_hh  [(size_t)N_NODES * D_HID];  // layer-1 GEMM output (fp16)
__device__ __half g_h2h [(size_t)N_NODES * D_OUT];  // layer-2 GEMM output (fp16)
__device__ float  g_dinv[N_NODES];
__device__ __half g_Ah  [(size_t)N_NODES * KP];     // fp16 A
__device__ __half g_BhT [(size_t)D_HID * KP];       // fp16 W1^T, n-major
__device__ __half g_BhT2[(size_t)D_OUT * KP];       // fp16 W2^T, n-major (separate!)
__device__ int    g_cnt [N_NODES];
__device__ int    g_row [N_NODES + 1];
__device__ int    g_fill[N_NODES];
__device__ int    g_csrc[N_EDGES];
__device__ float  g_cw  [N_EDGES];
__device__ int    g_bsum[256];
__device__ int    g_bpre[256];

// ---------------- side stream + events (static init; no device memory) ----------------
static cudaStream_t s_side = 0;
static cudaEvent_t  s_ev[6] = {0, 0, 0, 0, 0, 0};
namespace {
struct SideInit {
    SideInit() {
        if (cudaStreamCreateWithFlags(&s_side, cudaStreamNonBlocking) != cudaSuccess)
            s_side = 0;
        for (int i = 0; i < 6; i++)
            if (cudaEventCreateWithFlags(&s_ev[i], cudaEventDisableTiming) != cudaSuccess)
                s_ev[i] = 0;
    }
};
static SideInit s_side_init;
}

// ---------------- degree count / CSR ----------------
__global__ void k_cnt_zero() {
    int i = blockIdx.x * blockDim.x + threadIdx.x;
    if (i < N_NODES) g_cnt[i] = 0;
}
__global__ void k_count(const int* __restrict__ ei) {
    int e = blockIdx.x * blockDim.x + threadIdx.x;
    if (e < N_EDGES) atomicAdd(&g_cnt[ei[N_EDGES + e]], 1);
}
__global__ __launch_bounds__(256)
void k_dinv_bsum() {
    __shared__ int sm[256];
    int idx = blockIdx.x * 256 + threadIdx.x;
    int c = 0;
    if (idx < N_NODES) {
        c = g_cnt[idx];
        g_dinv[idx] = rsqrtf(1.0f + (float)c);
    }
    sm[threadIdx.x] = c;
    __syncthreads();
    for (int off = 128; off > 0; off >>= 1) {
        if (threadIdx.x < off) sm[threadIdx.x] += sm[threadIdx.x + off];
        __syncthreads();
    }
    if (threadIdx.x == 0) g_bsum[blockIdx.x] = sm[0];
}
__global__ __launch_bounds__(256)
void k_scan_bsum() {
    __shared__ int sm[256];
    int t = threadIdx.x;
    sm[t] = (t < NB) ? g_bsum[t] : 0;
    __syncthreads();
    for (int off = 1; off < 256; off <<= 1) {
        int v = (t >= off) ? sm[t - off] : 0;
        __syncthreads();
        sm[t] += v;
        __syncthreads();
    }
    int own = (t < NB) ? g_bsum[t] : 0;
    if (t < NB) g_bpre[t] = sm[t] - own;
    if (t == 255) g_row[N_NODES] = sm[255];
}
__global__ __launch_bounds__(256)
void k_rowfill() {
    __shared__ int sm[256];
    int idx = blockIdx.x * 256 + threadIdx.x;
    int t = threadIdx.x;
    int val = (idx < N_NODES) ? g_cnt[idx] : 0;
    sm[t] = val;
    __syncthreads();
    for (int off = 1; off < 256; off <<= 1) {
        int v = (t >= off) ? sm[t - off] : 0;
        __syncthreads();
        sm[t] += v;
        __syncthreads();
    }
    if (idx < N_NODES) {
        int r = g_bpre[blockIdx.x] + sm[t] - val;
        g_row[idx]  = r;
        g_fill[idx] = r;
    }
}
__global__ void k_fill(const int* __restrict__ ei) {
    int e = blockIdx.x * blockDim.x + threadIdx.x;
    if (e < N_EDGES) {
        int s = ei[e];
        int d = ei[N_EDGES + e];
        int pos = atomicAdd(&g_fill[d], 1);
        g_csrc[pos] = s;
        g_cw[pos]   = g_dinv[s] * g_dinv[d];
    }
}

// ---------------- packing ----------------
__global__ void k_pack_x(const float* __restrict__ x) {
    size_t idx = (size_t)blockIdx.x * blockDim.x + threadIdx.x;
    if (idx < (size_t)N_NODES * 64) {
        size_t m = idx >> 6;
        int c8 = (int)(idx & 63) * 8;
        const float* src = x + m * 512 + c8;
        float4 v0 = *(const float4*)src;
        float4 v1 = *(const float4*)(src + 4);
        __half2 h[4] = {
            __floats2half2_rn(v0.x, v0.y), __floats2half2_rn(v0.z, v0.w),
            __floats2half2_rn(v1.x, v1.y), __floats2half2_rn(v1.z, v1.w) };
        *(uint4*)(g_Ah + m * KP + c8) = *(uint4*)h;
    }
}
template <int N>
__device__ __forceinline__
void packB_body(const float* __restrict__ W, __half* __restrict__ dst) {
    int idx = blockIdx.x * blockDim.x + threadIdx.x;
    if (idx < 512 * N) {
        int k = idx / N, n = idx % N;
        dst[(size_t)n * KP + k] = __float2half(W[idx]);
    }
}
__global__ void k_pack_W1(const float* __restrict__ W) { packB_body<D_HID>(W, g_BhT); }
__global__ void k_pack_W2(const float* __restrict__ W) { packB_body<D_OUT>(W, g_BhT2); }

// ---------------- mma.sync m16n8k16 + ldmatrix ----------------
__device__ __forceinline__
void mma16816(float* d, const uint32_t* a, const uint32_t* b) {
    asm volatile(
        "mma.sync.aligned.m16n8k16.row.col.f32.f16.f16.f32 "
        "{%0,%1,%2,%3}, {%4,%5,%6,%7}, {%8,%9}, {%0,%1,%2,%3};\n"
        : "+f"(d[0]), "+f"(d[1]), "+f"(d[2]), "+f"(d[3])
        : "r"(a[0]), "r"(a[1]), "r"(a[2]), "r"(a[3]),
          "r"(b[0]), "r"(b[1]));
}
__device__ __forceinline__
void ldsm_x4(uint32_t* r, uint32_t addr) {
    asm volatile("ldmatrix.sync.aligned.m8n8.x4.shared.b16 {%0,%1,%2,%3}, [%4];"
                 : "=r"(r[0]), "=r"(r[1]), "=r"(r[2]), "=r"(r[3]) : "r"(addr));
}
__device__ __forceinline__
void ldsm_x2(uint32_t* r, uint32_t addr) {
    asm volatile("ldmatrix.sync.aligned.m8n8.x2.shared.b16 {%0,%1}, [%2];"
                 : "=r"(r[0]), "=r"(r[1]) : "r"(addr));
}
__device__ __forceinline__ uint32_t smem_u32(const void* p) {
    uint32_t a;
    asm("{ .reg .u64 t; cvta.to.shared.u64 t, %1; cvt.u32.u64 %0, t; }"
        : "=r"(a) : "l"(p));
    return a;
}

// ---------------- tensor-core GEMM: Ch[:, colOff + blockIdx.x*128 ...] ----------------
template <int N>
__device__ __forceinline__
void gemm_mma_body(const __half* __restrict__ Ah, const __half* __restrict__ BhT,
                   __half* __restrict__ Ch, int colOff) {
    constexpr int BM = 128, BK = 32, PITCH = 40;
    __shared__ __half As[2][BM][PITCH];
    __shared__ __half Bs[2][BM][PITCH];

    const int tid  = threadIdx.x;
    const int lane = tid & 31;
    const int wid  = tid >> 5;
    const int warp_m = wid >> 2;
    const int warp_n = wid & 3;
    const int rowBase = blockIdx.y * BM;
    const int colBase = colOff + blockIdx.x * BM;

    const int lg  = lane >> 2;
    const int lc2 = (lane & 3) * 2;

    const int rA = warp_m * 64 + (lane & 15);
    const int cA = (lane >> 4) * 8;
    const int rB = warp_n * 32 + (lane & 7);
    const int cB = ((lane >> 3) & 1) * 8;

    const int r0 = tid >> 2,  s0 = (tid & 3) * 8;
    const int r1 = r0 + 64;
    const uint4 z4 = make_uint4(0, 0, 0, 0);

    float acc[4][4][4];
    #pragma unroll
    for (int i = 0; i < 4; i++)
        #pragma unroll
        for (int j = 0; j < 4; j++)
            #pragma unroll
            for (int q = 0; q < 4; q++) acc[i][j][q] = 0.0f;

    uint4 na0, na1, nb0, nb1;
    {
        int gm0 = rowBase + r0, gm1 = rowBase + r1;
        na0 = (gm0 < N_NODES) ? *(const uint4*)(Ah + (size_t)gm0 * KP + s0) : z4;
        na1 = (gm1 < N_NODES) ? *(const uint4*)(Ah + (size_t)gm1 * KP + s0) : z4;
        nb0 = *(const uint4*)(BhT + (size_t)(colBase + r0) * KP + s0);
        nb1 = *(const uint4*)(BhT + (size_t)(colBase + r1) * KP + s0);
        *(uint4*)&As[0][r0][s0] = na0;
        *(uint4*)&As[0][r1][s0] = na1;
        *(uint4*)&Bs[0][r0][s0] = nb0;
        *(uint4*)&Bs[0][r1][s0] = nb1;
    }
    __syncthreads();

    constexpr int NIT = KP / BK;   // 16
    for (int t = 0; t < NIT; t++) {
        const int buf = t & 1;

        if (t + 1 < NIT) {
            const int k0 = (t + 1) * BK;
            int gm0 = rowBase + r0, gm1 = rowBase + r1;
            na0 = (gm0 < N_NODES) ? *(const uint4*)(Ah + (size_t)gm0 * KP + k0 + s0) : z4;
            na1 = (gm1 < N_NODES) ? *(const uint4*)(Ah + (size_t)gm1 * KP + k0 + s0) : z4;
            nb0 = *(const uint4*)(BhT + (size_t)(colBase + r0) * KP + k0 + s0);
            nb1 = *(const uint4*)(BhT + (size_t)(colBase + r1) * KP + k0 + s0);
        }

        #pragma unroll
        for (int ks = 0; ks < 2; ks++) {
            const int c = ks * 16;
            uint32_t afr[4][4], bfr[4][2];
            #pragma unroll
            for (int mf = 0; mf < 4; mf++)
                ldsm_x4(afr[mf], smem_u32(&As[buf][rA + mf * 16][c + cA]));
            #pragma unroll
            for (int nf = 0; nf < 4; nf++)
                ldsm_x2(bfr[nf], smem_u32(&Bs[buf][rB + nf * 8][c + cB]));
            #pragma unroll
            for (int mf = 0; mf < 4; mf++)
                #pragma unroll
                for (int nf = 0; nf < 4; nf++)
                    mma16816(acc[mf][nf], afr[mf], bfr[nf]);
        }

        if (t + 1 < NIT) {
            const int nbuf = buf ^ 1;
            *(uint4*)&As[nbuf][r0][s0] = na0;
            *(uint4*)&As[nbuf][r1][s0] = na1;
            *(uint4*)&Bs[nbuf][r0][s0] = nb0;
            *(uint4*)&Bs[nbuf][r1][s0] = nb1;
        }
        __syncthreads();
    }

    #pragma unroll
    for (int mf = 0; mf < 4; mf++) {
        #pragma unroll
        for (int hh = 0; hh < 2; hh++) {
            int m = rowBase + warp_m * 64 + mf * 16 + lg + hh * 8;
            if (m < N_NODES) {
                #pragma unroll
                for (int nf = 0; nf < 4; nf++) {
                    int n = colBase + warp_n * 32 + nf * 8 + lc2;
                    *(__half2*)(Ch + (size_t)m * N + n) =
                        __floats2half2_rn(acc[mf][nf][hh * 2 + 0], acc[mf][nf][hh * 2 + 1]);
                }
            }
        }
    }
}

__global__ __launch_bounds__(256)
void k_mma_l1(int colOff) { gemm_mma_body<D_HID>(g_Ah, g_BhT, g_hh, colOff); }
__global__ __launch_bounds__(256)
void k_mma_l2(int colOff) { gemm_mma_body<D_OUT>(g_Ah, g_BhT2, g_h2h, colOff); }

// ---------------- CSR gather layer 1 (4 cols/thread): writes fp16 A ----------------
// covers cols [colBase, colBase + 4*blockDim.x)
__global__ void k_gather_l1(const float* __restrict__ b1, int colBase) {
    int i = blockIdx.x;
    int col = colBase + threadIdx.x * 4;
    float s = g_dinv[i];
    float ss = s * s;

    __half2 hv2[2];
    *(uint2*)hv2 = *(const uint2*)(g_hh + (size_t)i * D_HID + col);
    float2 h0 = __half22float2(hv2[0]);
    float2 h1 = __half22float2(hv2[1]);
    float4 bv = *(const float4*)(b1 + col);
    float4 acc = make_float4(fmaf(h0.x, ss, bv.x), fmaf(h0.y, ss, bv.y),
                             fmaf(h1.x, ss, bv.z), fmaf(h1.y, ss, bv.w));

    int beg = g_row[i], end = g_row[i + 1];
    int j = beg;
    for (; j + 3 < end; j += 4) {
        int   s0 = g_csrc[j],     s1 = g_csrc[j + 1];
        int   s2 = g_csrc[j + 2], s3 = g_csrc[j + 3];
        float w0 = g_cw[j],       w1 = g_cw[j + 1];
        float w2 = g_cw[j + 2],   w3 = g_cw[j + 3];
        uint2 r0 = *(const uint2*)(g_hh + (size_t)s0 * D_HID + col);
        uint2 r1 = *(const uint2*)(g_hh + (size_t)s1 * D_HID + col);
        uint2 r2 = *(const uint2*)(g_hh + (size_t)s2 * D_HID + col);
        uint2 r3 = *(const uint2*)(g_hh + (size_t)s3 * D_HID + col);
        const __half2* p0 = (const __half2*)&r0;
        const __half2* p1 = (const __half2*)&r1;
        const __half2* p2 = (const __half2*)&r2;
        const __half2* p3 = (const __half2*)&r3;
        float2 a;
        a = __half22float2(p0[0]); acc.x = fmaf(a.x, w0, acc.x); acc.y = fmaf(a.y, w0, acc.y);
        a = __half22float2(p0[1]); acc.z = fmaf(a.x, w0, acc.z); acc.w = fmaf(a.y, w0, acc.w);
        a = __half22float2(p1[0]); acc.x = fmaf(a.x, w1, acc.x); acc.y = fmaf(a.y, w1, acc.y);
        a = __half22float2(p1[1]); acc.z = fmaf(a.x, w1, acc.z); acc.w = fmaf(a.y, w1, acc.w);
        a = __half22float2(p2[0]); acc.x = fmaf(a.x, w2, acc.x); acc.y = fmaf(a.y, w2, acc.y);
        a = __half22float2(p2[1]); acc.z = fmaf(a.x, w2, acc.z); acc.w = fmaf(a.y, w2, acc.w);
        a = __half22float2(p3[0]); acc.x = fmaf(a.x, w3, acc.x); acc.y = fmaf(a.y, w3, acc.y);
        a = __half22float2(p3[1]); acc.z = fmaf(a.x, w3, acc.z); acc.w = fmaf(a.y, w3, acc.w);
    }
    for (; j < end; j++) {
        int   sj = g_csrc[j];
        float w  = g_cw[j];
        uint2 r = *(const uint2*)(g_hh + (size_t)sj * D_HID + col);
        const __half2* p = (const __half2*)&r;
        float2 a0 = __half22float2(p[0]);
        float2 a1 = __half22float2(p[1]);
        acc.x = fmaf(a0.x, w, acc.x);
        acc.y = fmaf(a0.y, w, acc.y);
        acc.z = fmaf(a1.x, w, acc.z);
        acc.w = fmaf(a1.y, w, acc.w);
    }
    acc.x = fmaxf(acc.x, 0.f); acc.y = fmaxf(acc.y, 0.f);
    acc.z = fmaxf(acc.z, 0.f); acc.w = fmaxf(acc.w, 0.f);

    __half2 h[2] = { __floats2half2_rn(acc.x, acc.y),
                     __floats2half2_rn(acc.z, acc.w) };
    *(uint2*)(g_Ah + (size_t)i * KP + col) = *(uint2*)h;
}

// ---------------- CSR gather layer 2 (2 cols/thread) -> out (fp32) ----------------
__global__ void k_gather_l2(const float* __restrict__ b2, float* __restrict__ out,
                            int colBase) {
    int i = blockIdx.x;
    int col = colBase + threadIdx.x * 2;
    float s = g_dinv[i];
    float ss = s * s;

    float2 hv = __half22float2(*(const __half2*)(g_h2h + (size_t)i * D_OUT + col));
    float2 bv = *(const float2*)(b2 + col);
    float2 acc = make_float2(fmaf(hv.x, ss, bv.x), fmaf(hv.y, ss, bv.y));

    int beg = g_row[i], end = g_row[i + 1];
    int j = beg;
    for (; j + 3 < end; j += 4) {
        int   s0 = g_csrc[j],     s1 = g_csrc[j + 1];
        int   s2 = g_csrc[j + 2], s3 = g_csrc[j + 3];
        float w0 = g_cw[j],       w1 = g_cw[j + 1];
        float w2 = g_cw[j + 2],   w3 = g_cw[j + 3];
        __half2 q0 = *(const __half2*)(g_h2h + (size_t)s0 * D_OUT + col);
        __half2 q1 = *(const __half2*)(g_h2h + (size_t)s1 * D_OUT + col);
        __half2 q2 = *(const __half2*)(g_h2h + (size_t)s2 * D_OUT + col);
        __half2 q3 = *(const __half2*)(g_h2h + (size_t)s3 * D_OUT + col);
        float2 a;
        a = __half22float2(q0); acc.x = fmaf(a.x, w0, acc.x); acc.y = fmaf(a.y, w0, acc.y);
        a = __half22float2(q1); acc.x = fmaf(a.x, w1, acc.x); acc.y = fmaf(a.y, w1, acc.y);
        a = __half22float2(q2); acc.x = fmaf(a.x, w2, acc.x); acc.y = fmaf(a.y, w2, acc.y);
        a = __half22float2(q3); acc.x = fmaf(a.x, w3, acc.x); acc.y = fmaf(a.y, w3, acc.y);
    }
    for (; j < end; j++) {
        int   sj = g_csrc[j];
        float w  = g_cw[j];
        float2 a = __half22float2(*(const __half2*)(g_h2h + (size_t)sj * D_OUT + col));
        acc.x = fmaf(a.x, w, acc.x);
        acc.y = fmaf(a.y, w, acc.y);
    }
    *(float2*)(out + (size_t)i * D_OUT + col) = acc;
}

// ---------------- launch: column-split pipelined fork/join ----------------
extern "C" void kernel_launch(void* const* d_in, const int* in_sizes, int n_in,
                              void* d_out, int out_size) {
    const float* x  = (const float*)d_in[0];
    const int*   ei = (const int*)d_in[1];     // int32 (JAX x64 disabled)
    const float* W1 = (const float*)d_in[2];
    const float* b1 = (const float*)d_in[3];
    const float* W2 = (const float*)d_in[4];
    const float* b2 = (const float*)d_in[5];
    float* out = (float*)d_out;

    bool ok = (s_side != 0);
    for (int i = 0; i < 6; i++) ok = ok && (s_ev[i] != 0);

    if (!ok) {
        // serial fallback (proven R14 order)
        k_cnt_zero<<<(N_NODES + 255) / 256, 256>>>();
        k_count<<<(N_EDGES + 255) / 256, 256>>>(ei);
        k_dinv_bsum<<<NB, 256>>>();
        k_scan_bsum<<<1, 256>>>();
        k_rowfill<<<NB, 256>>>();
        k_fill<<<(N_EDGES + 255) / 256, 256>>>(ei);
        k_pack_x<<<(int)(((size_t)N_NODES * 64 + 255) / 256), 256>>>(x);
        k_pack_W1<<<(512 * D_HID + 255) / 256, 256>>>(W1);
        k_mma_l1<<<dim3(4, (N_NODES + 127) / 128), 256>>>(0);
        k_gather_l1<<<N_NODES, 128>>>(b1, 0);
        k_pack_W2<<<(512 * D_OUT + 255) / 256, 256>>>(W2);
        k_mma_l2<<<dim3(2, (N_NODES + 127) / 128), 256>>>(0);
        k_gather_l2<<<N_NODES, 128>>>(b2, out, 0);
        return;
    }

    cudaEvent_t evF = s_ev[0], evJ = s_ev[1], evA = s_ev[2],
                evGA = s_ev[3], evC = s_ev[4], evGC = s_ev[5];
    cudaStream_t side = s_side;
    const dim3 gridRows((unsigned)1, (N_NODES + 127) / 128);

    // fork
    cudaEventRecord(evF, 0);
    cudaStreamWaitEvent(side, evF, 0);

    // side: CSR build + pack_W2 (independent of layer-1 GEMM path)
    k_cnt_zero<<<(N_NODES + 255) / 256, 256, 0, side>>>();
    k_count<<<(N_EDGES + 255) / 256, 256, 0, side>>>(ei);
    k_dinv_bsum<<<NB, 256, 0, side>>>();
    k_scan_bsum<<<1, 256, 0, side>>>();
    k_rowfill<<<NB, 256, 0, side>>>();
    k_fill<<<(N_EDGES + 255) / 256, 256, 0, side>>>(ei);
    k_pack_W2<<<(512 * D_OUT + 255) / 256, 256, 0, side>>>(W2);
    cudaEventRecord(evJ, side);

    // main: pack + GEMM1 half A (cols 0-255)
    k_pack_x<<<(int)(((size_t)N_NODES * 64 + 255) / 256), 256>>>(x);
    k_pack_W1<<<(512 * D_HID + 255) / 256, 256>>>(W1);
    k_mma_l1<<<dim3(2, gridRows.y), 256>>>(0);
    cudaEventRecord(evA, 0);
    // main: GEMM1 half B (cols 256-511) runs concurrently with side gather
    k_mma_l1<<<dim3(2, gridRows.y), 256>>>(256);

    // side: gather half A (needs CSR [stream order] + mma_l1a [evA])
    cudaStreamWaitEvent(side, evA, 0);
    k_gather_l1<<<N_NODES, 64, 0, side>>>(b1, 0);       // cols 0-255
    cudaEventRecord(evGA, side);

    // main: gather half B (needs CSR via evJ + mma_l1b [stream order])
    cudaStreamWaitEvent(0, evJ, 0);
    k_gather_l1<<<N_NODES, 64>>>(b1, 256);              // cols 256-511

    // main: GEMM2 half A (needs full g_Ah: half B in-order, half A via evGA)
    cudaStreamWaitEvent(0, evGA, 0);
    k_mma_l2<<<dim3(1, gridRows.y), 256>>>(0);          // cols 0-127
    cudaEventRecord(evC, 0);
    k_mma_l2<<<dim3(1, gridRows.y), 256>>>(128);        // cols 128-255

    // side: gather2 half A concurrent with mma_l2b
    cudaStreamWaitEvent(side, evC, 0);
    k_gather_l2<<<N_NODES, 64, 0, side>>>(b2, out, 0);  // cols 0-127
    cudaEventRecord(evGC, side);

    // main: gather2 half B, then join side
    k_gather_l2<<<N_NODES, 64>>>(b2, out, 128);         // cols 128-255
    cudaStreamWaitEvent(0, evGC, 0);
}

// round 17
// speedup vs baseline: 8.0810x; 1.0581x over previous
#include <cuda_runtime.h>
#include <cuda_fp16.h>
#include <cstdint>

#define N_NODES 50000
#define N_EDGES 400000
#define D_IN    512
#define D_HID   512
#define D_OUT   256
#define KP      512    // plain fp16 GEMM
#define NB      196    // scan blocks: 196*256 >= 50000

// ---------------- scratch (device globals; referenced ONLY from device code) ----------------
__device__ __half g_hh  [(size_t)N_NODES * D_HID];  // layer-1 GEMM output (fp16)
__device__ __half g_h2h [(size_t)N_NODES * D_OUT];  // layer-2 GEMM output (fp16)
__device__ float  g_dinv[N_NODES];
__device__ __half g_Ah  [(size_t)N_NODES * KP];     // fp16 A
__device__ __half g_BhT [(size_t)D_HID * KP];       // fp16 W1^T, n-major
__device__ __half g_BhT2[(size_t)D_OUT * KP];       // fp16 W2^T, n-major
__device__ int    g_cnt [N_NODES];
__device__ int    g_row [N_NODES + 1];
__device__ int    g_fill[N_NODES];
__device__ int    g_csrc[N_EDGES];
__device__ float  g_cw  [N_EDGES];
__device__ int    g_bsum[256];
__device__ int    g_bpre[256];

// ---------------- side stream + events (static init; no device memory) ----------------
static cudaStream_t s_side = 0;
static cudaEvent_t  s_ev_fork = 0, s_ev_join = 0;
namespace {
struct SideInit {
    SideInit() {
        if (cudaStreamCreateWithFlags(&s_side, cudaStreamNonBlocking) != cudaSuccess)
            s_side = 0;
        if (cudaEventCreateWithFlags(&s_ev_fork, cudaEventDisableTiming) != cudaSuccess)
            s_ev_fork = 0;
        if (cudaEventCreateWithFlags(&s_ev_join, cudaEventDisableTiming) != cudaSuccess)
            s_ev_join = 0;
    }
};
static SideInit s_side_init;
}

// ---------------- degree count / CSR ----------------
__global__ void k_cnt_zero() {
    int i = blockIdx.x * blockDim.x + threadIdx.x;
    if (i < N_NODES) g_cnt[i] = 0;
}
__global__ void k_count(const int* __restrict__ ei) {
    int e = blockIdx.x * blockDim.x + threadIdx.x;
    if (e < N_EDGES) atomicAdd(&g_cnt[ei[N_EDGES + e]], 1);
}
__global__ __launch_bounds__(256)
void k_dinv_bsum() {
    __shared__ int sm[256];
    int idx = blockIdx.x * 256 + threadIdx.x;
    int c = 0;
    if (idx < N_NODES) {
        c = g_cnt[idx];
        g_dinv[idx] = rsqrtf(1.0f + (float)c);
    }
    sm[threadIdx.x] = c;
    __syncthreads();
    for (int off = 128; off > 0; off >>= 1) {
        if (threadIdx.x < off) sm[threadIdx.x] += sm[threadIdx.x + off];
        __syncthreads();
    }
    if (threadIdx.x == 0) g_bsum[blockIdx.x] = sm[0];
}
__global__ __launch_bounds__(256)
void k_scan_bsum() {
    __shared__ int sm[256];
    int t = threadIdx.x;
    sm[t] = (t < NB) ? g_bsum[t] : 0;
    __syncthreads();
    for (int off = 1; off < 256; off <<= 1) {
        int v = (t >= off) ? sm[t - off] : 0;
        __syncthreads();
        sm[t] += v;
        __syncthreads();
    }
    int own = (t < NB) ? g_bsum[t] : 0;
    if (t < NB) g_bpre[t] = sm[t] - own;
    if (t == 255) g_row[N_NODES] = sm[255];
}
__global__ __launch_bounds__(256)
void k_rowfill() {
    __shared__ int sm[256];
    int idx = blockIdx.x * 256 + threadIdx.x;
    int t = threadIdx.x;
    int val = (idx < N_NODES) ? g_cnt[idx] : 0;
    sm[t] = val;
    __syncthreads();
    for (int off = 1; off < 256; off <<= 1) {
        int v = (t >= off) ? sm[t - off] : 0;
        __syncthreads();
        sm[t] += v;
        __syncthreads();
    }
    if (idx < N_NODES) {
        int r = g_bpre[blockIdx.x] + sm[t] - val;
        g_row[idx]  = r;
        g_fill[idx] = r;
    }
}
__global__ void k_fill(const int* __restrict__ ei) {
    int e = blockIdx.x * blockDim.x + threadIdx.x;
    if (e < N_EDGES) {
        int s = ei[e];
        int d = ei[N_EDGES + e];
        int pos = atomicAdd(&g_fill[d], 1);
        g_csrc[pos] = s;
        g_cw[pos]   = g_dinv[s] * g_dinv[d];
    }
}

// ---------------- packing ----------------
__global__ void k_pack_x(const float* __restrict__ x) {
    size_t idx = (size_t)blockIdx.x * blockDim.x + threadIdx.x;
    if (idx < (size_t)N_NODES * 64) {
        size_t m = idx >> 6;
        int c8 = (int)(idx & 63) * 8;
        const float* src = x + m * 512 + c8;
        float4 v0 = *(const float4*)src;
        float4 v1 = *(const float4*)(src + 4);
        __half2 h[4] = {
            __floats2half2_rn(v0.x, v0.y), __floats2half2_rn(v0.z, v0.w),
            __floats2half2_rn(v1.x, v1.y), __floats2half2_rn(v1.z, v1.w) };
        *(uint4*)(g_Ah + m * KP + c8) = *(uint4*)h;
    }
}
template <int N>
__device__ __forceinline__
void packB_body(const float* __restrict__ W, __half* __restrict__ dst) {
    int idx = blockIdx.x * blockDim.x + threadIdx.x;
    if (idx < 512 * N) {
        int k = idx / N, n = idx % N;
        dst[(size_t)n * KP + k] = __float2half(W[idx]);
    }
}
__global__ void k_pack_W1(const float* __restrict__ W) { packB_body<D_HID>(W, g_BhT); }
__global__ void k_pack_W2(const float* __restrict__ W) { packB_body<D_OUT>(W, g_BhT2); }

// ---------------- mma.sync m16n8k16 + ldmatrix + cp.async ----------------
__device__ __forceinline__
void mma16816(float* d, const uint32_t* a, const uint32_t* b) {
    asm volatile(
        "mma.sync.aligned.m16n8k16.row.col.f32.f16.f16.f32 "
        "{%0,%1,%2,%3}, {%4,%5,%6,%7}, {%8,%9}, {%0,%1,%2,%3};\n"
        : "+f"(d[0]), "+f"(d[1]), "+f"(d[2]), "+f"(d[3])
        : "r"(a[0]), "r"(a[1]), "r"(a[2]), "r"(a[3]),
          "r"(b[0]), "r"(b[1]));
}
__device__ __forceinline__
void ldsm_x4(uint32_t* r, uint32_t addr) {
    asm volatile("ldmatrix.sync.aligned.m8n8.x4.shared.b16 {%0,%1,%2,%3}, [%4];"
                 : "=r"(r[0]), "=r"(r[1]), "=r"(r[2]), "=r"(r[3]) : "r"(addr));
}
__device__ __forceinline__
void ldsm_x2(uint32_t* r, uint32_t addr) {
    asm volatile("ldmatrix.sync.aligned.m8n8.x2.shared.b16 {%0,%1}, [%2];"
                 : "=r"(r[0]), "=r"(r[1]) : "r"(addr));
}
__device__ __forceinline__ uint32_t smem_u32(const void* p) {
    uint32_t a;
    asm("{ .reg .u64 t; cvta.to.shared.u64 t, %1; cvt.u32.u64 %0, t; }"
        : "=r"(a) : "l"(p));
    return a;
}
__device__ __forceinline__
void cp_async16(uint32_t dst, const void* src, int src_sz) {
    asm volatile("cp.async.cg.shared.global [%0], [%1], 16, %2;"
                 :: "r"(dst), "l"(src), "r"(src_sz) : "memory");
}
__device__ __forceinline__ void cp_commit() {
    asm volatile("cp.async.commit_group;" ::: "memory");
}
__device__ __forceinline__ void cp_wait0() {
    asm volatile("cp.async.wait_group 0;" ::: "memory");
}

// ---------------- tensor-core GEMM: Ch[M,N] = half(A[M,512] @ B[512,N]) ----------------
// 128x128 block tile, BK=32, 256 threads, cp.async double-buffered staging,
// __launch_bounds__(256,2) for 2 CTAs/SM.
template <int N>
__device__ __forceinline__
void gemm_mma_body(const __half* __restrict__ Ah, const __half* __restrict__ BhT,
                   __half* __restrict__ Ch) {
    constexpr int BM = 128, BK = 32, PITCH = 40;
    __shared__ __half As[2][BM][PITCH];
    __shared__ __half Bs[2][BM][PITCH];

    const int tid  = threadIdx.x;
    const int lane = tid & 31;
    const int wid  = tid >> 5;
    const int warp_m = wid >> 2;
    const int warp_n = wid & 3;
    const int rowBase = blockIdx.y * BM;
    const int colBase = blockIdx.x * BM;

    const int lg  = lane >> 2;
    const int lc2 = (lane & 3) * 2;

    const int rA = warp_m * 64 + (lane & 15);
    const int cA = (lane >> 4) * 8;
    const int rB = warp_n * 32 + (lane & 7);
    const int cB = ((lane >> 3) & 1) * 8;

    const int r0 = tid >> 2,  s0 = (tid & 3) * 8;
    const int r1 = r0 + 64;
    const bool v0 = (rowBase + r0) < N_NODES;
    const bool v1 = (rowBase + r1) < N_NODES;
    const int gm0 = v0 ? (rowBase + r0) : 0;   // clamped, zero-filled via src_sz=0
    const int gm1 = v1 ? (rowBase + r1) : 0;
    const int sz0 = v0 ? 16 : 0;
    const int sz1 = v1 ? 16 : 0;

    const __half* aSrc0 = Ah + (size_t)gm0 * KP + s0;
    const __half* aSrc1 = Ah + (size_t)gm1 * KP + s0;
    const __half* bSrc0 = BhT + (size_t)(colBase + r0) * KP + s0;
    const __half* bSrc1 = BhT + (size_t)(colBase + r1) * KP + s0;

    float acc[4][4][4];
    #pragma unroll
    for (int i = 0; i < 4; i++)
        #pragma unroll
        for (int j = 0; j < 4; j++)
            #pragma unroll
            for (int q = 0; q < 4; q++) acc[i][j][q] = 0.0f;

    // stage tile 0 into buf 0
    cp_async16(smem_u32(&As[0][r0][s0]), aSrc0, sz0);
    cp_async16(smem_u32(&As[0][r1][s0]), aSrc1, sz1);
    cp_async16(smem_u32(&Bs[0][r0][s0]), bSrc0, 16);
    cp_async16(smem_u32(&Bs[0][r1][s0]), bSrc1, 16);
    cp_commit();
    cp_wait0();
    __syncthreads();

    constexpr int NIT = KP / BK;   // 16
    for (int t = 0; t < NIT; t++) {
        const int buf = t & 1;

        if (t + 1 < NIT) {
            const int k0 = (t + 1) * BK;
            const int nbuf = buf ^ 1;
            cp_async16(smem_u32(&As[nbuf][r0][s0]), aSrc0 + k0, sz0);
            cp_async16(smem_u32(&As[nbuf][r1][s0]), aSrc1 + k0, sz1);
            cp_async16(smem_u32(&Bs[nbuf][r0][s0]), bSrc0 + k0, 16);
            cp_async16(smem_u32(&Bs[nbuf][r1][s0]), bSrc1 + k0, 16);
            cp_commit();
        }

        #pragma unroll
        for (int ks = 0; ks < 2; ks++) {
            const int c = ks * 16;
            uint32_t afr[4][4], bfr[4][2];
            #pragma unroll
            for (int mf = 0; mf < 4; mf++)
                ldsm_x4(afr[mf], smem_u32(&As[buf][rA + mf * 16][c + cA]));
            #pragma unroll
            for (int nf = 0; nf < 4; nf++)
                ldsm_x2(bfr[nf], smem_u32(&Bs[buf][rB + nf * 8][c + cB]));
            #pragma unroll
            for (int mf = 0; mf < 4; mf++)
                #pragma unroll
                for (int nf = 0; nf < 4; nf++)
                    mma16816(acc[mf][nf], afr[mf], bfr[nf]);
        }

        if (t + 1 < NIT) cp_wait0();
        __syncthreads();
    }

    #pragma unroll
    for (int mf = 0; mf < 4; mf++) {
        #pragma unroll
        for (int hh = 0; hh < 2; hh++) {
            int m = rowBase + warp_m * 64 + mf * 16 + lg + hh * 8;
            if (m < N_NODES) {
                #pragma unroll
                for (int nf = 0; nf < 4; nf++) {
                    int n = colBase + warp_n * 32 + nf * 8 + lc2;
                    *(__half2*)(Ch + (size_t)m * N + n) =
                        __floats2half2_rn(acc[mf][nf][hh * 2 + 0], acc[mf][nf][hh * 2 + 1]);
                }
            }
        }
    }
}

__global__ __launch_bounds__(256, 2)
void k_mma_l1() { gemm_mma_body<D_HID>(g_Ah, g_BhT, g_hh); }
__global__ __launch_bounds__(256, 2)
void k_mma_l2() { gemm_mma_body<D_OUT>(g_Ah, g_BhT2, g_h2h); }

// ---------------- CSR gather layer 1 (4-wide edge unroll): writes fp16 A ----------------
__global__ __launch_bounds__(128)
void k_gather_l1(const float* __restrict__ b1) {
    int i = blockIdx.x;
    int col = threadIdx.x * 4;
    float s = g_dinv[i];
    float ss = s * s;

    __half2 hv2[2];
    *(uint2*)hv2 = *(const uint2*)(g_hh + (size_t)i * D_HID + col);
    float2 h0 = __half22float2(hv2[0]);
    float2 h1 = __half22float2(hv2[1]);
    float4 bv = *(const float4*)(b1 + col);
    float4 acc = make_float4(fmaf(h0.x, ss, bv.x), fmaf(h0.y, ss, bv.y),
                             fmaf(h1.x, ss, bv.z), fmaf(h1.y, ss, bv.w));

    int beg = g_row[i], end = g_row[i + 1];
    int j = beg;
    for (; j + 3 < end; j += 4) {
        int   s0 = g_csrc[j],     s1 = g_csrc[j + 1];
        int   s2 = g_csrc[j + 2], s3 = g_csrc[j + 3];
        float w0 = g_cw[j],       w1 = g_cw[j + 1];
        float w2 = g_cw[j + 2],   w3 = g_cw[j + 3];
        uint2 r0 = *(const uint2*)(g_hh + (size_t)s0 * D_HID + col);
        uint2 r1 = *(const uint2*)(g_hh + (size_t)s1 * D_HID + col);
        uint2 r2 = *(const uint2*)(g_hh + (size_t)s2 * D_HID + col);
        uint2 r3 = *(const uint2*)(g_hh + (size_t)s3 * D_HID + col);
        const __half2* p0 = (const __half2*)&r0;
        const __half2* p1 = (const __half2*)&r1;
        const __half2* p2 = (const __half2*)&r2;
        const __half2* p3 = (const __half2*)&r3;
        float2 a;
        a = __half22float2(p0[0]); acc.x = fmaf(a.x, w0, acc.x); acc.y = fmaf(a.y, w0, acc.y);
        a = __half22float2(p0[1]); acc.z = fmaf(a.x, w0, acc.z); acc.w = fmaf(a.y, w0, acc.w);
        a = __half22float2(p1[0]); acc.x = fmaf(a.x, w1, acc.x); acc.y = fmaf(a.y, w1, acc.y);
        a = __half22float2(p1[1]); acc.z = fmaf(a.x, w1, acc.z); acc.w = fmaf(a.y, w1, acc.w);
        a = __half22float2(p2[0]); acc.x = fmaf(a.x, w2, acc.x); acc.y = fmaf(a.y, w2, acc.y);
        a = __half22float2(p2[1]); acc.z = fmaf(a.x, w2, acc.z); acc.w = fmaf(a.y, w2, acc.w);
        a = __half22float2(p3[0]); acc.x = fmaf(a.x, w3, acc.x); acc.y = fmaf(a.y, w3, acc.y);
        a = __half22float2(p3[1]); acc.z = fmaf(a.x, w3, acc.z); acc.w = fmaf(a.y, w3, acc.w);
    }
    for (; j < end; j++) {
        int   sj = g_csrc[j];
        float w  = g_cw[j];
        uint2 r = *(const uint2*)(g_hh + (size_t)sj * D_HID + col);
        const __half2* p = (const __half2*)&r;
        float2 a0 = __half22float2(p[0]);
        float2 a1 = __half22float2(p[1]);
        acc.x = fmaf(a0.x, w, acc.x);
        acc.y = fmaf(a0.y, w, acc.y);
        acc.z = fmaf(a1.x, w, acc.z);
        acc.w = fmaf(a1.y, w, acc.w);
    }
    acc.x = fmaxf(acc.x, 0.f); acc.y = fmaxf(acc.y, 0.f);
    acc.z = fmaxf(acc.z, 0.f); acc.w = fmaxf(acc.w, 0.f);

    __half2 h[2] = { __floats2half2_rn(acc.x, acc.y),
                     __floats2half2_rn(acc.z, acc.w) };
    *(uint2*)(g_Ah + (size_t)i * KP + col) = *(uint2*)h;
}

// ---------------- CSR gather layer 2 (4-wide edge unroll) -> out (fp32) ----------------
__global__ __launch_bounds__(128)
void k_gather_l2(const float* __restrict__ b2, float* __restrict__ out) {
    int i = blockIdx.x;
    int col = threadIdx.x * 2;
    float s = g_dinv[i];
    float ss = s * s;

    float2 hv = __half22float2(*(const __half2*)(g_h2h + (size_t)i * D_OUT + col));
    float2 bv = *(const float2*)(b2 + col);
    float2 acc = make_float2(fmaf(hv.x, ss, bv.x), fmaf(hv.y, ss, bv.y));

    int beg = g_row[i], end = g_row[i + 1];
    int j = beg;
    for (; j + 3 < end; j += 4) {
        int   s0 = g_csrc[j],     s1 = g_csrc[j + 1];
        int   s2 = g_csrc[j + 2], s3 = g_csrc[j + 3];
        float w0 = g_cw[j],       w1 = g_cw[j + 1];
        float w2 = g_cw[j + 2],   w3 = g_cw[j + 3];
        __half2 q0 = *(const __half2*)(g_h2h + (size_t)s0 * D_OUT + col);
        __half2 q1 = *(const __half2*)(g_h2h + (size_t)s1 * D_OUT + col);
        __half2 q2 = *(const __half2*)(g_h2h + (size_t)s2 * D_OUT + col);
        __half2 q3 = *(const __half2*)(g_h2h + (size_t)s3 * D_OUT + col);
        float2 a;
        a = __half22float2(q0); acc.x = fmaf(a.x, w0, acc.x); acc.y = fmaf(a.y, w0, acc.y);
        a = __half22float2(q1); acc.x = fmaf(a.x, w1, acc.x); acc.y = fmaf(a.y, w1, acc.y);
        a = __half22float2(q2); acc.x = fmaf(a.x, w2, acc.x); acc.y = fmaf(a.y, w2, acc.y);
        a = __half22float2(q3); acc.x = fmaf(a.x, w3, acc.x); acc.y = fmaf(a.y, w3, acc.y);
    }
    for (; j < end; j++) {
        int   sj = g_csrc[j];
        float w  = g_cw[j];
        float2 a = __half22float2(*(const __half2*)(g_h2h + (size_t)sj * D_OUT + col));
        acc.x = fmaf(a.x, w, acc.x);
        acc.y = fmaf(a.y, w, acc.y);
    }
    *(float2*)(out + (size_t)i * D_OUT + col) = acc;
}

// ---------------- launch ----------------
extern "C" void kernel_launch(void* const* d_in, const int* in_sizes, int n_in,
                              void* d_out, int out_size) {
    const float* x  = (const float*)d_in[0];
    const int*   ei = (const int*)d_in[1];     // int32 (JAX x64 disabled)
    const float* W1 = (const float*)d_in[2];
    const float* b1 = (const float*)d_in[3];
    const float* W2 = (const float*)d_in[4];
    const float* b2 = (const float*)d_in[5];
    float* out = (float*)d_out;

    const bool fork = (s_side != 0 && s_ev_fork != 0 && s_ev_join != 0);
    cudaStream_t side = fork ? s_side : 0;

    if (fork) {
        cudaEventRecord(s_ev_fork, 0);
        cudaStreamWaitEvent(side, s_ev_fork, 0);
    }

    // ---- side stream: CSR build + pack_W2 (independent of layer-1 GEMM path) ----
    k_cnt_zero<<<(N_NODES + 255) / 256, 256, 0, side>>>();
    k_count<<<(N_EDGES + 255) / 256, 256, 0, side>>>(ei);
    k_dinv_bsum<<<NB, 256, 0, side>>>();
    k_scan_bsum<<<1, 256, 0, side>>>();
    k_rowfill<<<NB, 256, 0, side>>>();
    k_fill<<<(N_EDGES + 255) / 256, 256, 0, side>>>(ei);
    k_pack_W2<<<(512 * D_OUT + 255) / 256, 256, 0, side>>>(W2);
    if (fork) cudaEventRecord(s_ev_join, side);

    // ---- main stream: pack + GEMM layer 1 ----
    {
        size_t tot = (size_t)N_NODES * 64;
        k_pack_x<<<(int)((tot + 255) / 256), 256>>>(x);
        k_pack_W1<<<(512 * D_HID + 255) / 256, 256>>>(W1);
        dim3 grid(D_HID / 128, (N_NODES + 127) / 128);
        k_mma_l1<<<grid, 256>>>();
    }

    // join: gather_l1 needs CSR (row/csrc/cw) + dinv + g_BhT2 packed
    if (fork) cudaStreamWaitEvent(0, s_ev_join, 0);

    k_gather_l1<<<N_NODES, 128>>>(b1);

    // layer 2
    {
        dim3 grid(D_OUT / 128, (N_NODES + 127) / 128);
        k_mma_l2<<<grid, 256>>>();
    }
    k_gather_l2<<<N_NODES, 128>>>(b2, out);
}